// round 12
// baseline (speedup 1.0000x reference)
#include <cuda_runtime.h>
#include <math.h>

#define NQ 16
#define NS 65536
#define BATCH 256
#define SLIM (BATCH * NS)
#define MLIM (BATCH * 3 * NQ * 4)

__device__ __align__(16) float g_state[SLIM];
__device__ __align__(16) float g_M[MLIM];
__device__ float g_P[48];
__device__ __align__(16) float g_F[BATCH * 2048];
__device__ __align__(16) float g_H[BATCH * 64];

typedef unsigned long long ull;

__device__ __forceinline__ float sigm(float x) { return 1.0f / (1.0f + expf(-x)); }

// ---- packed f32x2 primitives ------------------------------------------------
__device__ __forceinline__ ull fpack(float x, float y) {
    ull r; asm("mov.b64 %0, {%1, %2};" : "=l"(r) : "f"(x), "f"(y)); return r;
}
__device__ __forceinline__ ull fbcast(float x) { return fpack(x, x); }
__device__ __forceinline__ void funpack(float& x, float& y, ull a) {
    asm("mov.b64 {%0, %1}, %2;" : "=f"(x), "=f"(y) : "l"(a));
}
__device__ __forceinline__ ull fma2(ull a, ull b, ull c) {
    ull d; asm("fma.rn.f32x2 %0, %1, %2, %3;" : "=l"(d) : "l"(a), "l"(b), "l"(c)); return d;
}
__device__ __forceinline__ ull mul2(ull a, ull b) {
    ull d; asm("mul.rn.f32x2 %0, %1, %2;" : "=l"(d) : "l"(a), "l"(b)); return d;
}

// Packed 2x2 gate / noisy-CNOT on N f32x2 regs (register-bit kb/cb/tb).
template <int N>
__device__ __forceinline__ void gate_p(ull* v, int kb, ull M00, ull M01, ull M10, ull M11) {
    #pragma unroll
    for (int i = 0; i < N; i++) if (!(i & kb)) {
        const int j = i | kb;
        ull a = v[i], c = v[j];
        v[i] = fma2(M01, c, mul2(M00, a));
        v[j] = fma2(M11, c, mul2(M10, a));
    }
}
template <int N>
__device__ __forceinline__ void cnot_p(ull* v, int cb, int tb, ull OM, ull PP) {
    #pragma unroll
    for (int i = 0; i < N; i++) if ((i & cb) && !(i & tb)) {
        const int j = i | tb;
        ull a = v[i], c = v[j];
        v[i] = fma2(PP, c, mul2(OM, a));
        v[j] = fma2(PP, a, mul2(OM, c));
    }
}
// ctrl outside regs (uniform or lane-varying coefficient packs), target bit tb.
template <int N>
__device__ __forceinline__ void cnot_p_ext(ull* v, int tb, ull OM, ull PP) {
    #pragma unroll
    for (int i = 0; i < N; i++) if (!(i & tb)) {
        const int j = i | tb;
        ull a = v[i], c = v[j];
        v[i] = fma2(PP, c, mul2(OM, a));
        v[j] = fma2(PP, a, mul2(OM, c));
    }
}

__global__ void dummy_kernel(float* outf, unsigned capF) {
    if (capF > 0) outf[0] = 0.f;
}

// ---------------------------------------------------------------------------
// MLP + gate matrices + sigmoid table (unchanged from R10).
// ---------------------------------------------------------------------------
__global__ void mlp_kernel(const float* __restrict__ X,
                           const float* __restrict__ rot,
                           const float* __restrict__ ent,
                           const float* __restrict__ W1,
                           const float* __restrict__ b1,
                           const float* __restrict__ W2,
                           const float* __restrict__ b2)
{
    __shared__ float sx[100];
    __shared__ float sa[64];
    __shared__ float sh[16];
    const int b = blockIdx.x;
    const int j = threadIdx.x;

    if (b == 0 && j < 45) g_P[j] = sigm(ent[j]);

    for (int k = j; k < 100; k += 64) sx[k] = X[b * 100 + k];
    __syncthreads();
    {
        float s = b1[j];
        #pragma unroll 4
        for (int k = 0; k < 100; k++) s = fmaf(sx[k], W1[k * 64 + j], s);
        sa[j] = s > 0.f ? s : 0.f;
    }
    __syncthreads();
    if (j < 16) {
        float s = b2[j];
        #pragma unroll 8
        for (int k = 0; k < 64; k++) s = fmaf(sa[k], W2[k * 16 + j], s);
        sh[j] = tanhf(s);
    }
    __syncthreads();
    if (j < 48) {
        const int l = j >> 4, q = j & 15;
        float hv = 0.5f * sh[q];
        float ax = rot[(l * 16 + q) * 3 + 0] * hv;
        float ay = rot[(l * 16 + q) * 3 + 1] * hv;
        float az = rot[(l * 16 + q) * 3 + 2] * hv;
        float cx, sx2, cy, sy, cz, sz;
        sincosf(ax, &sx2, &cx);
        sincosf(ay, &sy,  &cy);
        sincosf(az, &sz,  &cz);
        float* m = &g_M[((b * 3 + l) * NQ + q) * 4];
        m[0] =  cx * cy * cz;
        m[1] = -sx2 * sy * sz;
        m[2] =  sx2 * sy * cz;
        m[3] =  cx * cy * sz;
    }
}

// ---------------------------------------------------------------------------
// Layer-0 closed form (unchanged from R10): F' (2048), H_0/H_1 (32 each).
// ---------------------------------------------------------------------------
__global__ void __launch_bounds__(256) prep_kernel()
{
    __shared__ float fA[2048], fB[2048];
    __shared__ float gg[2][32];
    const int b = blockIdx.x;
    const unsigned t = threadIdx.x;
    const float* M = &g_M[b * 3 * 64];

    float ph = 1.f;
    #pragma unroll
    for (int q = 3; q < 11; q++) ph *= M[q * 4 + (((t >> (q - 3)) & 1) ? 2 : 0)];
    #pragma unroll
    for (int r = 0; r < 8; r++) {
        float pr = ph;
        pr *= M[0 + ((r & 1) ? 2 : 0)];
        pr *= M[4 + ((r & 2) ? 2 : 0)];
        pr *= M[8 + ((r & 4) ? 2 : 0)];
        fA[t * 8 + r] = pr;
    }
    __syncthreads();

    float* cur = fA;
    float* nxt = fB;
    #pragma unroll
    for (int i = 0; i < 10; i++) {
        const float p = g_P[i], om = 1.f - p;
        const unsigned cb = 1u << i, tb = 1u << (i + 1);
        #pragma unroll
        for (int k = 0; k < 8; k++) {
            const unsigned l = t + 256u * k;
            const float a = cur[l];
            nxt[l] = (l & cb) ? (om * a + p * cur[l ^ tb]) : a;
        }
        __syncthreads();
        float* tmp = cur; cur = nxt; nxt = tmp;
    }
    #pragma unroll
    for (int k = 0; k < 8; k++) {
        const unsigned l = t + 256u * k;
        g_F[b * 2048 + l] = cur[l];
    }

    if (t < 32) {
        float g = 1.f;
        #pragma unroll
        for (int q = 11; q < 16; q++) g *= M[q * 4 + (((t >> (q - 11)) & 1) ? 2 : 0)];
        gg[0][t] = g;
    }
    __syncthreads();
    if (t < 32) {
        const float p = g_P[10];
        gg[1][t] = (1.f - p) * gg[0][t] + p * gg[0][t ^ 1u];
    }
    __syncthreads();
    #pragma unroll
    for (int i = 11; i < 15; i++) {
        const float p = g_P[i], om = 1.f - p;
        const unsigned cb = 1u << (i - 11), tb = 1u << (i - 10);
        float r = 0.f;
        if (t < 64) {
            const unsigned vv = t >> 5, h = t & 31u;
            const float a = gg[vv][h];
            r = (h & cb) ? (om * a + p * gg[vv][h ^ tb]) : a;
        }
        __syncthreads();
        if (t < 64) gg[t >> 5][t & 31u] = r;
        __syncthreads();
    }
    if (t < 64) g_H[b * 64 + t] = gg[t >> 5][t & 31u];
}

// ---------------------------------------------------------------------------
// Pass A (f32x2-packed): slab = bits 0..12 (8192 states), 256 threads x
// 16 f32x2 regs, pack lane = state bit 0. Register phases (f32x2-index = s>>1):
//   m0: regs = state bits 1..4, thread = bits 5..12
//   m1: regs = bits 5..8,  thread = bits 1..4 | 9..12
//   m2: regs = bits 9..12, thread = bits 1..8
// Two padded-smem transposes (same index math as R10, float2 elements).
// G0 (pack-lane gate) is folded into the load as scalar FMAs; in MODE 1 its
// coefficients also absorb the H-factor scale. C0 (ctrl = lane) uses
// lane-varying coefficient packs. Ops: m0: G1..4, C0ext(lane) C1 C2 C3
//   m1: G5..8, C4ext C5 C6 C7 | m2: G9..12, C8ext C9 C10 C11, store.
// ---------------------------------------------------------------------------
#define SMEM_U64 5376  /* 43008 B */
template <int LAYER, int MODE>
__global__ void __launch_bounds__(256) passA_kernel()
{
    __shared__ ull sm[SMEM_U64];
    const int hi = blockIdx.x & 7;    // state bits 13..15
    const int b  = blockIdx.x >> 3;
    const unsigned t = threadIdx.x;
    const float* M = &g_M[(b * 3 + LAYER) * 64];
    const float* P = &g_P[LAYER * 15];
    const unsigned base = ((unsigned)b << 16) + ((unsigned)hi << 13);

    ull v[16];
    // ---- load + G0 (scalar, pre-pack) ----
    {
        float m00 = M[0], m01 = M[1], m10 = M[2], m11 = M[3];
        const float* src;
        if (MODE == 1) {
            const float hval = g_H[(unsigned)b * 64u + ((t >> 5) & 1u) * 32u
                                   + (((unsigned)hi << 2) | ((t >> 6) & 3u))];
            m00 *= hval; m01 *= hval; m10 *= hval; m11 *= hval;
            src = &g_F[(unsigned)b * 2048u + ((t & 63u) << 5)];
        } else {
            src = &g_state[base + (t << 5)];
        }
        #pragma unroll
        for (int k = 0; k < 8; k++) {
            const float4 u = *(const float4*)&src[4 * k];
            v[2*k]   = fpack(fmaf(m00, u.x, m01 * u.y), fmaf(m10, u.x, m11 * u.y));
            v[2*k+1] = fpack(fmaf(m00, u.z, m01 * u.w), fmaf(m10, u.z, m11 * u.w));
        }
    }
    // ---- m0: G1..G4 (reg bits 0..3), C0 (ctrl=lane), C1..C3 ----
    gate_p<16>(v, 1, fbcast(M[4]),  fbcast(M[5]),  fbcast(M[6]),  fbcast(M[7]));
    gate_p<16>(v, 2, fbcast(M[8]),  fbcast(M[9]),  fbcast(M[10]), fbcast(M[11]));
    gate_p<16>(v, 4, fbcast(M[12]), fbcast(M[13]), fbcast(M[14]), fbcast(M[15]));
    gate_p<16>(v, 8, fbcast(M[16]), fbcast(M[17]), fbcast(M[18]), fbcast(M[19]));
    cnot_p_ext<16>(v, 1, fpack(1.f, 1.f - P[0]), fpack(0.f, P[0]));   // C0
    cnot_p<16>(v, 1, 2, fbcast(1.f - P[1]), fbcast(P[1]));            // C1
    cnot_p<16>(v, 2, 4, fbcast(1.f - P[2]), fbcast(P[2]));            // C2
    cnot_p<16>(v, 4, 8, fbcast(1.f - P[3]), fbcast(P[3]));            // C3

    // ---- T1: 16B writes, stride-20 reads (padded, conflict-free) ----
    {
        ulonglong2* s4 = (ulonglong2*)sm;
        const unsigned w4 = t * 10u + 8u * (t >> 4);
        #pragma unroll
        for (int m = 0; m < 8; m++) s4[w4 + m] = make_ulonglong2(v[2*m], v[2*m+1]);
    }
    __syncthreads();
    {
        const unsigned rbase = (t & 15u) + 336u * (t >> 4);
        #pragma unroll
        for (int r = 0; r < 16; r++) v[r] = sm[rbase + 20u * r];
    }
    // ---- m1: G5..G8, C4ext C5 C6 C7 ----
    gate_p<16>(v, 1, fbcast(M[20]), fbcast(M[21]), fbcast(M[22]), fbcast(M[23]));
    gate_p<16>(v, 2, fbcast(M[24]), fbcast(M[25]), fbcast(M[26]), fbcast(M[27]));
    gate_p<16>(v, 4, fbcast(M[28]), fbcast(M[29]), fbcast(M[30]), fbcast(M[31]));
    gate_p<16>(v, 8, fbcast(M[32]), fbcast(M[33]), fbcast(M[34]), fbcast(M[35]));
    {
        const bool c = (t & 8u) != 0;   // ctrl = state bit 4
        cnot_p_ext<16>(v, 1, fbcast(c ? 1.f - P[4] : 1.f), fbcast(c ? P[4] : 0.f));
    }
    cnot_p<16>(v, 1, 2, fbcast(1.f - P[5]), fbcast(P[5]));
    cnot_p<16>(v, 2, 4, fbcast(1.f - P[6]), fbcast(P[6]));
    cnot_p<16>(v, 4, 8, fbcast(1.f - P[7]), fbcast(P[7]));

    __syncthreads();  // WAR before buffer reuse

    // ---- T2: stride-16 writes, stride-272 reads ----
    {
        const unsigned wbase = (t & 15u) + 272u * (t >> 4);
        #pragma unroll
        for (int r = 0; r < 16; r++) sm[wbase + 16u * r] = v[r];
    }
    __syncthreads();
    {
        #pragma unroll
        for (int r = 0; r < 16; r++) v[r] = sm[272u * r + t];
    }
    // ---- m2: G9..G12, C8ext C9 C10 C11 ----
    gate_p<16>(v, 1, fbcast(M[36]), fbcast(M[37]), fbcast(M[38]), fbcast(M[39]));
    gate_p<16>(v, 2, fbcast(M[40]), fbcast(M[41]), fbcast(M[42]), fbcast(M[43]));
    gate_p<16>(v, 4, fbcast(M[44]), fbcast(M[45]), fbcast(M[46]), fbcast(M[47]));
    gate_p<16>(v, 8, fbcast(M[48]), fbcast(M[49]), fbcast(M[50]), fbcast(M[51]));
    {
        const bool c = (t & 128u) != 0;  // ctrl = state bit 8
        cnot_p_ext<16>(v, 1, fbcast(c ? 1.f - P[8] : 1.f), fbcast(c ? P[8] : 0.f));
    }
    cnot_p<16>(v, 1, 2, fbcast(1.f - P[9]),  fbcast(P[9]));
    cnot_p<16>(v, 2, 4, fbcast(1.f - P[10]), fbcast(P[10]));
    cnot_p<16>(v, 4, 8, fbcast(1.f - P[11]), fbcast(P[11]));

    // coalesced 8B stores: state = base | r<<9 | t<<1 | lane
    #pragma unroll
    for (int r = 0; r < 16; r++)
        *(ull*)&g_state[base + ((unsigned)r << 9) + (t << 1)] = v[r];
}

// ---------------------------------------------------------------------------
// Pass B (f32x2-packed): bits 13..15. Each thread: 4 consecutive lows
// (2 f32x2 chains) x 8 highs = 16 f32x2 regs. G13..15, C12ext(ctrl bit12),
// C13, C14. All I/O via 16B ulonglong2.
// ---------------------------------------------------------------------------
__device__ __forceinline__ void gate_b(ull* w, int kb, ull M00, ull M01, ull M10, ull M11) {
    #pragma unroll
    for (int i = 0; i < 8; i++) if (!(i & kb)) {
        const int j = i | kb;
        #pragma unroll
        for (int c = 0; c < 2; c++) {
            ull a = w[i*2+c], d = w[j*2+c];
            w[i*2+c] = fma2(M01, d, mul2(M00, a));
            w[j*2+c] = fma2(M11, d, mul2(M10, a));
        }
    }
}
__device__ __forceinline__ void cnot_b(ull* w, int cb, int tb, ull OM, ull PP) {
    #pragma unroll
    for (int i = 0; i < 8; i++) if ((i & cb) && !(i & tb)) {
        const int j = i | tb;
        #pragma unroll
        for (int c = 0; c < 2; c++) {
            ull a = w[i*2+c], d = w[j*2+c];
            w[i*2+c] = fma2(PP, d, mul2(OM, a));
            w[j*2+c] = fma2(PP, a, mul2(OM, d));
        }
    }
}
__device__ __forceinline__ void cnot_b_ext(ull* w, int tb, ull OM, ull PP) {
    #pragma unroll
    for (int i = 0; i < 8; i++) if (!(i & tb)) {
        const int j = i | tb;
        #pragma unroll
        for (int c = 0; c < 2; c++) {
            ull a = w[i*2+c], d = w[j*2+c];
            w[i*2+c] = fma2(PP, d, mul2(OM, a));
            w[j*2+c] = fma2(PP, a, mul2(OM, d));
        }
    }
}

template <int LAYER, bool OUT>
__global__ void __launch_bounds__(256) passB_kernel(float* __restrict__ outf,
                                                    unsigned capF, int mode)
{
    const int blk = blockIdx.x & 7;     // low bits 10..12
    const int b = blockIdx.x >> 3;
    const unsigned t = threadIdx.x;
    const unsigned low = ((unsigned)blk << 10) | (t << 2);
    const float* M = &g_M[(b * 3 + LAYER) * 64];
    const float* P = &g_P[LAYER * 15];
    const unsigned base = ((unsigned)b << 16) + low;

    ull w[16];
    #pragma unroll
    for (int k = 0; k < 8; k++) {
        const ulonglong2 u = *(const ulonglong2*)&g_state[base + ((unsigned)k << 13)];
        w[2*k] = u.x; w[2*k+1] = u.y;
    }

    gate_b(w, 1, fbcast(M[52]), fbcast(M[53]), fbcast(M[54]), fbcast(M[55]));  // G13
    gate_b(w, 2, fbcast(M[56]), fbcast(M[57]), fbcast(M[58]), fbcast(M[59]));  // G14
    gate_b(w, 4, fbcast(M[60]), fbcast(M[61]), fbcast(M[62]), fbcast(M[63]));  // G15
    {
        const bool c = (low & 4096u) != 0;  // C12 ctrl = bit 12
        cnot_b_ext(w, 1, fbcast(c ? 1.f - P[12] : 1.f), fbcast(c ? P[12] : 0.f));
    }
    cnot_b(w, 1, 2, fbcast(1.f - P[13]), fbcast(P[13]));  // C13
    cnot_b(w, 2, 4, fbcast(1.f - P[14]), fbcast(P[14]));  // C14

    if (OUT) {
        if (mode == 1) {
            #pragma unroll
            for (int k = 0; k < 8; k++) {
                const unsigned idx = base + ((unsigned)k << 13);
                const unsigned p2 = 2u * idx;
                if (p2 + 7u < capF) {
                    float f0, f1, f2, f3;
                    funpack(f0, f1, w[2*k]);
                    funpack(f2, f3, w[2*k+1]);
                    *(float4*)&outf[p2]     = make_float4(f0, 0.f, f1, 0.f);
                    *(float4*)&outf[p2 + 4] = make_float4(f2, 0.f, f3, 0.f);
                }
            }
        } else {
            #pragma unroll
            for (int k = 0; k < 8; k++) {
                const unsigned idx = base + ((unsigned)k << 13);
                if (idx + 3u < capF)
                    *(ulonglong2*)&outf[idx] = make_ulonglong2(w[2*k], w[2*k+1]);
            }
        }
    } else {
        #pragma unroll
        for (int k = 0; k < 8; k++)
            *(ulonglong2*)&g_state[base + ((unsigned)k << 13)] =
                make_ulonglong2(w[2*k], w[2*k+1]);
    }
}

// ---------------------------------------------------------------------------
extern "C" void kernel_launch(void* const* d_in, const int* in_sizes, int n_in,
                              void* d_out, int out_size)
{
    static const long long want[7] = {25600, 144, 45, 6400, 64, 1024, 16};
    const float* ptr[7] = {0, 0, 0, 0, 0, 0, 0};

    bool bound = false;
    for (int scale = 1; scale <= 4 && !bound; scale *= 4) {
        const float* tmp[7] = {0, 0, 0, 0, 0, 0, 0};
        int m = 0;
        for (int i = 0; i < n_in; i++) {
            long long s = (long long)in_sizes[i];
            for (int j = 0; j < 7; j++) {
                if (!tmp[j] && s == want[j] * scale) { tmp[j] = (const float*)d_in[i]; m++; break; }
            }
        }
        if (m == 7) { for (int j = 0; j < 7; j++) ptr[j] = tmp[j]; bound = true; }
    }
    if (!bound && n_in >= 7) {
        for (int j = 0; j < 7; j++) ptr[j] = (const float*)d_in[j];
        bound = true;
    }

    float* outf = (float*)d_out;

    long long os = (long long)out_size;
    unsigned capF;
    int mode;
    if (os >= 33554432LL)      { mode = 1; capF = 33554432u; }
    else if (os == 16777216LL) { mode = 0; capF = 16777216u; }
    else {
        mode = 0;
        long long c = os > 0 ? os : 0;
        if (c > 33554432LL) c = 33554432LL;
        capF = (unsigned)c;
    }

    if (!bound || !outf) {
        dummy_kernel<<<1, 32>>>(outf, capF);
        return;
    }

    mlp_kernel<<<BATCH, 64>>>(ptr[0], ptr[1], ptr[2], ptr[3], ptr[4], ptr[5], ptr[6]);
    prep_kernel<<<BATCH, 256>>>();

    const int GA = 8 * BATCH;  // 2048 blocks (slab = bits 0..12)
    const int GB = 8 * BATCH;  // 2048 blocks (4 lows/thread over bits 0..12)
    passA_kernel<1, 1><<<GA, 256>>>();
    passB_kernel<1, false><<<GB, 256>>>(outf, capF, mode);
    passA_kernel<2, 0><<<GA, 256>>>();
    passB_kernel<2, true ><<<GB, 256>>>(outf, capF, mode);
}

// round 13
// speedup vs baseline: 1.0784x; 1.0784x over previous
#include <cuda_runtime.h>
#include <math.h>

#define NQ 16
#define NS 65536
#define BATCH 256
#define SLIM (BATCH * NS)
#define MLIM (BATCH * 3 * NQ * 4)

__device__ __align__(16) float g_state[SLIM];
__device__ __align__(16) float g_M[MLIM];
__device__ float g_P[48];
__device__ __align__(16) float g_F[BATCH * 2048];
__device__ __align__(16) float g_H[BATCH * 64];

typedef unsigned long long ull;

__device__ __forceinline__ float sigm(float x) { return 1.0f / (1.0f + expf(-x)); }

// ---- packed f32x2 primitives ----
__device__ __forceinline__ ull fpack(float x, float y) {
    ull r; asm("mov.b64 %0, {%1, %2};" : "=l"(r) : "f"(x), "f"(y)); return r;
}
__device__ __forceinline__ ull fbcast(float x) { return fpack(x, x); }
__device__ __forceinline__ void funpack(float& x, float& y, ull a) {
    asm("mov.b64 {%0, %1}, %2;" : "=f"(x), "=f"(y) : "l"(a));
}
__device__ __forceinline__ ull fma2(ull a, ull b, ull c) {
    ull d; asm("fma.rn.f32x2 %0, %1, %2, %3;" : "=l"(d) : "l"(a), "l"(b), "l"(c)); return d;
}
__device__ __forceinline__ ull mul2(ull a, ull b) {
    ull d; asm("mul.rn.f32x2 %0, %1, %2;" : "=l"(d) : "l"(a), "l"(b)); return d;
}

template <int N>
__device__ __forceinline__ void gate_p(ull* v, int kb, ull M00, ull M01, ull M10, ull M11) {
    #pragma unroll
    for (int i = 0; i < N; i++) if (!(i & kb)) {
        const int j = i | kb;
        ull a = v[i], c = v[j];
        v[i] = fma2(M01, c, mul2(M00, a));
        v[j] = fma2(M11, c, mul2(M10, a));
    }
}
template <int N>
__device__ __forceinline__ void cnot_p(ull* v, int cb, int tb, ull OM, ull PP) {
    #pragma unroll
    for (int i = 0; i < N; i++) if ((i & cb) && !(i & tb)) {
        const int j = i | tb;
        ull a = v[i], c = v[j];
        v[i] = fma2(PP, c, mul2(OM, a));
        v[j] = fma2(PP, a, mul2(OM, c));
    }
}
template <int N>
__device__ __forceinline__ void cnot_p_ext(ull* v, int tb, ull OM, ull PP) {
    #pragma unroll
    for (int i = 0; i < N; i++) if (!(i & tb)) {
        const int j = i | tb;
        ull a = v[i], c = v[j];
        v[i] = fma2(PP, c, mul2(OM, a));
        v[j] = fma2(PP, a, mul2(OM, c));
    }
}

__global__ void dummy_kernel(float* outf, unsigned capF) {
    if (capF > 0) outf[0] = 0.f;
}

// ---------------------------------------------------------------------------
// MLP + gate matrices + sigmoid table (unchanged).
// ---------------------------------------------------------------------------
__global__ void mlp_kernel(const float* __restrict__ X,
                           const float* __restrict__ rot,
                           const float* __restrict__ ent,
                           const float* __restrict__ W1,
                           const float* __restrict__ b1,
                           const float* __restrict__ W2,
                           const float* __restrict__ b2)
{
    __shared__ float sx[100];
    __shared__ float sa[64];
    __shared__ float sh[16];
    const int b = blockIdx.x;
    const int j = threadIdx.x;

    if (b == 0 && j < 45) g_P[j] = sigm(ent[j]);

    for (int k = j; k < 100; k += 64) sx[k] = X[b * 100 + k];
    __syncthreads();
    {
        float s = b1[j];
        #pragma unroll 4
        for (int k = 0; k < 100; k++) s = fmaf(sx[k], W1[k * 64 + j], s);
        sa[j] = s > 0.f ? s : 0.f;
    }
    __syncthreads();
    if (j < 16) {
        float s = b2[j];
        #pragma unroll 8
        for (int k = 0; k < 64; k++) s = fmaf(sa[k], W2[k * 16 + j], s);
        sh[j] = tanhf(s);
    }
    __syncthreads();
    if (j < 48) {
        const int l = j >> 4, q = j & 15;
        float hv = 0.5f * sh[q];
        float ax = rot[(l * 16 + q) * 3 + 0] * hv;
        float ay = rot[(l * 16 + q) * 3 + 1] * hv;
        float az = rot[(l * 16 + q) * 3 + 2] * hv;
        float cx, sx2, cy, sy, cz, sz;
        sincosf(ax, &sx2, &cx);
        sincosf(ay, &sy,  &cy);
        sincosf(az, &sz,  &cz);
        float* m = &g_M[((b * 3 + l) * NQ + q) * 4];
        m[0] =  cx * cy * cz;
        m[1] = -sx2 * sy * sz;
        m[2] =  sx2 * sy * cz;
        m[3] =  cx * cy * sz;
    }
}

// ---------------------------------------------------------------------------
// Layer-0 closed form (unchanged): F' (2048), H_0/H_1 (32 each) per batch.
// ---------------------------------------------------------------------------
__global__ void __launch_bounds__(256) prep_kernel()
{
    __shared__ float fA[2048], fB[2048];
    __shared__ float gg[2][32];
    const int b = blockIdx.x;
    const unsigned t = threadIdx.x;
    const float* M = &g_M[b * 3 * 64];

    float ph = 1.f;
    #pragma unroll
    for (int q = 3; q < 11; q++) ph *= M[q * 4 + (((t >> (q - 3)) & 1) ? 2 : 0)];
    #pragma unroll
    for (int r = 0; r < 8; r++) {
        float pr = ph;
        pr *= M[0 + ((r & 1) ? 2 : 0)];
        pr *= M[4 + ((r & 2) ? 2 : 0)];
        pr *= M[8 + ((r & 4) ? 2 : 0)];
        fA[t * 8 + r] = pr;
    }
    __syncthreads();

    float* cur = fA;
    float* nxt = fB;
    #pragma unroll
    for (int i = 0; i < 10; i++) {
        const float p = g_P[i], om = 1.f - p;
        const unsigned cb = 1u << i, tb = 1u << (i + 1);
        #pragma unroll
        for (int k = 0; k < 8; k++) {
            const unsigned l = t + 256u * k;
            const float a = cur[l];
            nxt[l] = (l & cb) ? (om * a + p * cur[l ^ tb]) : a;
        }
        __syncthreads();
        float* tmp = cur; cur = nxt; nxt = tmp;
    }
    #pragma unroll
    for (int k = 0; k < 8; k++) {
        const unsigned l = t + 256u * k;
        g_F[b * 2048 + l] = cur[l];
    }

    if (t < 32) {
        float g = 1.f;
        #pragma unroll
        for (int q = 11; q < 16; q++) g *= M[q * 4 + (((t >> (q - 11)) & 1) ? 2 : 0)];
        gg[0][t] = g;
    }
    __syncthreads();
    if (t < 32) {
        const float p = g_P[10];
        gg[1][t] = (1.f - p) * gg[0][t] + p * gg[0][t ^ 1u];
    }
    __syncthreads();
    #pragma unroll
    for (int i = 11; i < 15; i++) {
        const float p = g_P[i], om = 1.f - p;
        const unsigned cb = 1u << (i - 11), tb = 1u << (i - 10);
        float r = 0.f;
        if (t < 64) {
            const unsigned vv = t >> 5, h = t & 31u;
            const float a = gg[vv][h];
            r = (h & cb) ? (om * a + p * gg[vv][h ^ tb]) : a;
        }
        __syncthreads();
        if (t < 64) gg[t >> 5][t & 31u] = r;
        __syncthreads();
    }
    if (t < 64) g_H[b * 64 + t] = gg[t >> 5][t & 31u];
}

// ---------------------------------------------------------------------------
// Pass A (packed, R10 footprint): slab = bits 0..11 (4096 states), 256 thr x
// 8 f32x2 regs. Phases: m0 pack=bit0 regs=bits1..3 (thread=bits4..11);
// m1 pack=bit4 regs=bits5..7; m2 pack=bit8 regs=bits9..11. Transposes reuse
// R10's proven padded float addressing. Pack-lane gates G0/G4/G8 fold into
// loads; pack-lane-ctrl CNOTs C0/C4/C8 use lane packs; external-ctrl C3/C7
// fold branchless at the transpose reads.
// ---------------------------------------------------------------------------
#define SMEM_FLOATS 5376
template <int LAYER, int MODE>
__global__ void __launch_bounds__(256) passA_kernel()
{
    __shared__ float sm[SMEM_FLOATS];
    const int hi = blockIdx.x & 15;   // state bits 12..15
    const int b  = blockIdx.x >> 4;
    const unsigned t = threadIdx.x;
    const float* M = &g_M[(b * 3 + LAYER) * 64];
    const float* P = &g_P[LAYER * 15];
    const unsigned base = ((unsigned)b << 16) + ((unsigned)hi << 12);

    ull v[8];
    float s[16];

    // ---- load + G0 fold (pack lane = bit 0) ----
    {
        float m00 = M[0], m01 = M[1], m10 = M[2], m11 = M[3];
        const float* src;
        if (MODE == 1) {
            const float hval = g_H[(unsigned)b * 64u + ((t >> 6) & 1u) * 32u
                                   + (((unsigned)hi << 1) | ((t >> 7) & 1u))];
            m00 *= hval; m01 *= hval; m10 *= hval; m11 *= hval;
            src = &g_F[(unsigned)b * 2048u + ((t & 127u) << 4)];
        } else {
            src = &g_state[base + (t << 4)];
        }
        #pragma unroll
        for (int k = 0; k < 4; k++) {
            const float4 u = *(const float4*)&src[4 * k];
            v[2*k]   = fpack(fmaf(m00, u.x, m01 * u.y), fmaf(m10, u.x, m11 * u.y));
            v[2*k+1] = fpack(fmaf(m00, u.z, m01 * u.w), fmaf(m10, u.z, m11 * u.w));
        }
    }
    // ---- m0: G1..G3 (reg bits 0..2 = state bits 1..3), C0(lane) C1 C2 ----
    gate_p<8>(v, 1, fbcast(M[4]),  fbcast(M[5]),  fbcast(M[6]),  fbcast(M[7]));
    gate_p<8>(v, 2, fbcast(M[8]),  fbcast(M[9]),  fbcast(M[10]), fbcast(M[11]));
    gate_p<8>(v, 4, fbcast(M[12]), fbcast(M[13]), fbcast(M[14]), fbcast(M[15]));
    cnot_p_ext<8>(v, 1, fpack(1.f, 1.f - P[0]), fpack(0.f, P[0]));   // C0 (0->1)
    cnot_p<8>(v, 1, 2, fbcast(1.f - P[1]), fbcast(P[1]));            // C1 (1->2)
    cnot_p<8>(v, 2, 4, fbcast(1.f - P[2]), fbcast(P[2]));            // C2 (2->3)

    // ---- T1 write (R10 addressing: float4, w4 = t*5 + 4*(t>>4)) ----
    #pragma unroll
    for (int i = 0; i < 8; i++) funpack(s[2*i], s[2*i+1], v[i]);
    {
        float4* s4 = (float4*)sm;
        const unsigned w4 = t * 5u + 4u * (t >> 4);
        #pragma unroll
        for (int k = 0; k < 4; k++)
            s4[w4 + k] = make_float4(s[4*k], s[4*k+1], s[4*k+2], s[4*k+3]);
    }
    __syncthreads();
    // ---- T1 read + G4 + C3 fold (pack lane = bit 4) ----
    {
        const unsigned rbase = (t & 15u) + 336u * (t >> 4);
        const float g00 = M[16], g01 = M[17], g10 = M[18], g11 = M[19];
        const bool c3 = (t & 8u) != 0;          // ctrl = state bit 3
        const float q3 = c3 ? P[3] : 0.f, o3 = 1.f - q3;
        #pragma unroll
        for (int j = 0; j < 8; j++) {
            const float a  = sm[rbase + 20u * (2*j)];
            const float bb = sm[rbase + 20u * (2*j+1)];
            const float lo = fmaf(g00, a, g01 * bb);
            const float hi2 = fmaf(g10, a, g11 * bb);
            v[j] = fpack(fmaf(o3, lo, q3 * hi2), fmaf(o3, hi2, q3 * lo));
        }
    }
    // ---- m1: G5..G7 (reg bits 0..2 = bits 5..7), C4(lane) C5 C6 ----
    gate_p<8>(v, 1, fbcast(M[20]), fbcast(M[21]), fbcast(M[22]), fbcast(M[23]));
    gate_p<8>(v, 2, fbcast(M[24]), fbcast(M[25]), fbcast(M[26]), fbcast(M[27]));
    gate_p<8>(v, 4, fbcast(M[28]), fbcast(M[29]), fbcast(M[30]), fbcast(M[31]));
    cnot_p_ext<8>(v, 1, fpack(1.f, 1.f - P[4]), fpack(0.f, P[4]));   // C4 (4->5)
    cnot_p<8>(v, 1, 2, fbcast(1.f - P[5]), fbcast(P[5]));            // C5 (5->6)
    cnot_p<8>(v, 2, 4, fbcast(1.f - P[6]), fbcast(P[6]));            // C6 (6->7)

    __syncthreads();  // WAR before buffer reuse

    // ---- T2 write (R10 addressing: scalar, wbase = (t&15)+272*(t>>4)) ----
    #pragma unroll
    for (int j = 0; j < 8; j++) funpack(s[2*j], s[2*j+1], v[j]);
    {
        const unsigned wbase = (t & 15u) + 272u * (t >> 4);
        #pragma unroll
        for (int r = 0; r < 16; r++) sm[wbase + 16u * r] = s[r];
    }
    __syncthreads();
    // ---- T2 read + G8 + C7 fold (pack lane = bit 8) ----
    {
        const float g00 = M[32], g01 = M[33], g10 = M[34], g11 = M[35];
        const bool c7 = (t & 128u) != 0;        // ctrl = state bit 7
        const float q7 = c7 ? P[7] : 0.f, o7 = 1.f - q7;
        #pragma unroll
        for (int j = 0; j < 8; j++) {
            const float a  = sm[272u * (2*j) + t];
            const float bb = sm[272u * (2*j+1) + t];
            const float lo = fmaf(g00, a, g01 * bb);
            const float hi2 = fmaf(g10, a, g11 * bb);
            v[j] = fpack(fmaf(o7, lo, q7 * hi2), fmaf(o7, hi2, q7 * lo));
        }
    }
    // ---- m2: G9..G11 (reg bits 0..2 = bits 9..11), C8(lane) C9 C10 ----
    gate_p<8>(v, 1, fbcast(M[36]), fbcast(M[37]), fbcast(M[38]), fbcast(M[39]));
    gate_p<8>(v, 2, fbcast(M[40]), fbcast(M[41]), fbcast(M[42]), fbcast(M[43]));
    gate_p<8>(v, 4, fbcast(M[44]), fbcast(M[45]), fbcast(M[46]), fbcast(M[47]));
    cnot_p_ext<8>(v, 1, fpack(1.f, 1.f - P[8]), fpack(0.f, P[8]));   // C8 (8->9)
    cnot_p<8>(v, 1, 2, fbcast(1.f - P[9]),  fbcast(P[9]));           // C9 (9->10)
    cnot_p<8>(v, 2, 4, fbcast(1.f - P[10]), fbcast(P[10]));          // C10 (10->11)

    // store: state = base | r<<8 | t, r = (j<<1)|lane  (coalesced STG.32)
    #pragma unroll
    for (int j = 0; j < 8; j++) {
        float f0, f1;
        funpack(f0, f1, v[j]);
        g_state[base + ((unsigned)(2*j)   << 8) + t] = f0;
        g_state[base + ((unsigned)(2*j+1) << 8) + t] = f1;
    }
}

// ---------------------------------------------------------------------------
// Pass B (packed): bits 12..15. 16 ull = 16 highs x 2 consecutive lows.
// Grid: blockIdx.x = b*8 + blk; low = blk<<9 | t<<1 (covers bits 0..11).
// GATES: this layer's G12..15. NEXTG: next layer's G12..15 (commute with
// next layer's low-bit pass). Then C11ext (ctrl bit 11, uniform), C12..C14.
// OUT: final output write per mode.
// ---------------------------------------------------------------------------
template <int LAYER, bool GATES, bool NEXTG, bool OUT>
__global__ void __launch_bounds__(256) passB_kernel(float* __restrict__ outf,
                                                    unsigned capF, int mode)
{
    const int blk = blockIdx.x & 7;      // low bits 9..11
    const int b = blockIdx.x >> 3;
    const unsigned t = threadIdx.x;
    const unsigned low = ((unsigned)blk << 9) | (t << 1);
    const float* M = &g_M[(b * 3 + LAYER) * 64];
    const float* P = &g_P[LAYER * 15];
    const unsigned base = ((unsigned)b << 16) + low;

    ull w[16];
    #pragma unroll
    for (int k = 0; k < 16; k++) w[k] = *(const ull*)&g_state[base + ((unsigned)k << 12)];

    if (GATES) {
        gate_p<16>(w, 1, fbcast(M[48]), fbcast(M[49]), fbcast(M[50]), fbcast(M[51]));  // G12
        gate_p<16>(w, 2, fbcast(M[52]), fbcast(M[53]), fbcast(M[54]), fbcast(M[55]));  // G13
        gate_p<16>(w, 4, fbcast(M[56]), fbcast(M[57]), fbcast(M[58]), fbcast(M[59]));  // G14
        gate_p<16>(w, 8, fbcast(M[60]), fbcast(M[61]), fbcast(M[62]), fbcast(M[63]));  // G15
    }
    {
        const bool c = (low & 2048u) != 0;   // C11 ctrl = bit 11
        const float q = c ? P[11] : 0.f;
        cnot_p_ext<16>(w, 1, fbcast(1.f - q), fbcast(q));            // C11 (11->12)
    }
    cnot_p<16>(w, 1, 2, fbcast(1.f - P[12]), fbcast(P[12]));         // C12 (12->13)
    cnot_p<16>(w, 2, 4, fbcast(1.f - P[13]), fbcast(P[13]));         // C13 (13->14)
    cnot_p<16>(w, 4, 8, fbcast(1.f - P[14]), fbcast(P[14]));         // C14 (14->15)

    if (NEXTG) {  // next layer's high-bit gates (commute with its low-bit pass)
        const float* M2 = &g_M[(b * 3 + LAYER + 1) * 64];
        gate_p<16>(w, 1, fbcast(M2[48]), fbcast(M2[49]), fbcast(M2[50]), fbcast(M2[51]));
        gate_p<16>(w, 2, fbcast(M2[52]), fbcast(M2[53]), fbcast(M2[54]), fbcast(M2[55]));
        gate_p<16>(w, 4, fbcast(M2[56]), fbcast(M2[57]), fbcast(M2[58]), fbcast(M2[59]));
        gate_p<16>(w, 8, fbcast(M2[60]), fbcast(M2[61]), fbcast(M2[62]), fbcast(M2[63]));
    }

    if (OUT) {
        if (mode == 1) {
            #pragma unroll
            for (int k = 0; k < 16; k++) {
                const unsigned idx = base + ((unsigned)k << 12);
                const unsigned p2 = 2u * idx;   // idx even -> 16B aligned
                if (p2 + 3u < capF) {
                    float f0, f1;
                    funpack(f0, f1, w[k]);
                    *(float4*)&outf[p2] = make_float4(f0, 0.f, f1, 0.f);
                }
            }
        } else {
            #pragma unroll
            for (int k = 0; k < 16; k++) {
                const unsigned idx = base + ((unsigned)k << 12);
                if (idx + 1u < capF) *(ull*)&outf[idx] = w[k];
            }
        }
    } else {
        #pragma unroll
        for (int k = 0; k < 16; k++)
            *(ull*)&g_state[base + ((unsigned)k << 12)] = w[k];
    }
}

// ---------------------------------------------------------------------------
extern "C" void kernel_launch(void* const* d_in, const int* in_sizes, int n_in,
                              void* d_out, int out_size)
{
    static const long long want[7] = {25600, 144, 45, 6400, 64, 1024, 16};
    const float* ptr[7] = {0, 0, 0, 0, 0, 0, 0};

    bool bound = false;
    for (int scale = 1; scale <= 4 && !bound; scale *= 4) {
        const float* tmp[7] = {0, 0, 0, 0, 0, 0, 0};
        int m = 0;
        for (int i = 0; i < n_in; i++) {
            long long s = (long long)in_sizes[i];
            for (int j = 0; j < 7; j++) {
                if (!tmp[j] && s == want[j] * scale) { tmp[j] = (const float*)d_in[i]; m++; break; }
            }
        }
        if (m == 7) { for (int j = 0; j < 7; j++) ptr[j] = tmp[j]; bound = true; }
    }
    if (!bound && n_in >= 7) {
        for (int j = 0; j < 7; j++) ptr[j] = (const float*)d_in[j];
        bound = true;
    }

    float* outf = (float*)d_out;

    long long os = (long long)out_size;
    unsigned capF;
    int mode;
    if (os >= 33554432LL)      { mode = 1; capF = 33554432u; }
    else if (os == 16777216LL) { mode = 0; capF = 16777216u; }
    else {
        mode = 0;
        long long c = os > 0 ? os : 0;
        if (c > 33554432LL) c = 33554432LL;
        capF = (unsigned)c;
    }

    if (!bound || !outf) {
        dummy_kernel<<<1, 32>>>(outf, capF);
        return;
    }

    mlp_kernel<<<BATCH, 64>>>(ptr[0], ptr[1], ptr[2], ptr[3], ptr[4], ptr[5], ptr[6]);
    prep_kernel<<<BATCH, 256>>>();

    const int GA = 16 * BATCH;  // 4096 blocks (slab bits 0..11)
    const int GB = 8 * BATCH;   // 2048 blocks (2 lows/thread)
    passA_kernel<1, 1><<<GA, 256>>>();                            // l1 low bits
    passB_kernel<1, true, true, false><<<GB, 256>>>(outf, capF, mode);  // l1 high + l2 G12..15
    passA_kernel<2, 0><<<GA, 256>>>();                            // l2 low bits
    passB_kernel<2, false, false, true><<<GB, 256>>>(outf, capF, mode); // l2 C11..14 + out
}

// round 14
// speedup vs baseline: 1.2743x; 1.1816x over previous
#include <cuda_runtime.h>
#include <math.h>

#define NQ 16
#define NS 65536
#define BATCH 256
#define SLIM (BATCH * NS)
#define MLIM (BATCH * 3 * NQ * 4)
#define VOFF 4194304u   /* V region offset (floats) inside g_state */

__device__ __align__(16) float g_state[SLIM];   // Y: [0,4M), V: [4M,12M)
__device__ __align__(16) float g_M[MLIM];
__device__ float g_P[48];
__device__ __align__(16) float g_F[BATCH * 2048];
__device__ __align__(16) float g_H[BATCH * 64];
__device__ __align__(16) float g_U[BATCH * 256];  // [b][j:8][w2:2][hi:16]

typedef unsigned long long ull;

__device__ __forceinline__ float sigm(float x) { return 1.0f / (1.0f + expf(-x)); }

// ---- packed f32x2 primitives ----
__device__ __forceinline__ ull fpack(float x, float y) {
    ull r; asm("mov.b64 %0, {%1, %2};" : "=l"(r) : "f"(x), "f"(y)); return r;
}
__device__ __forceinline__ ull fbcast(float x) { return fpack(x, x); }
__device__ __forceinline__ void funpack(float& x, float& y, ull a) {
    asm("mov.b64 {%0, %1}, %2;" : "=f"(x), "=f"(y) : "l"(a));
}
__device__ __forceinline__ ull fma2(ull a, ull b, ull c) {
    ull d; asm("fma.rn.f32x2 %0, %1, %2, %3;" : "=l"(d) : "l"(a), "l"(b), "l"(c)); return d;
}
__device__ __forceinline__ ull mul2(ull a, ull b) {
    ull d; asm("mul.rn.f32x2 %0, %1, %2;" : "=l"(d) : "l"(a), "l"(b)); return d;
}

template <int N>
__device__ __forceinline__ void gate_p(ull* v, int kb, ull M00, ull M01, ull M10, ull M11) {
    #pragma unroll
    for (int i = 0; i < N; i++) if (!(i & kb)) {
        const int j = i | kb;
        ull a = v[i], c = v[j];
        v[i] = fma2(M01, c, mul2(M00, a));
        v[j] = fma2(M11, c, mul2(M10, a));
    }
}
template <int N>
__device__ __forceinline__ void cnot_p(ull* v, int cb, int tb, ull OM, ull PP) {
    #pragma unroll
    for (int i = 0; i < N; i++) if ((i & cb) && !(i & tb)) {
        const int j = i | tb;
        ull a = v[i], c = v[j];
        v[i] = fma2(PP, c, mul2(OM, a));
        v[j] = fma2(PP, a, mul2(OM, c));
    }
}
template <int N>
__device__ __forceinline__ void cnot_p_ext(ull* v, int tb, ull OM, ull PP) {
    #pragma unroll
    for (int i = 0; i < N; i++) if (!(i & tb)) {
        const int j = i | tb;
        ull a = v[i], c = v[j];
        v[i] = fma2(PP, c, mul2(OM, a));
        v[j] = fma2(PP, a, mul2(OM, c));
    }
}

__global__ void dummy_kernel(float* outf, unsigned capF) {
    if (capF > 0) outf[0] = 0.f;
}

// ---------------------------------------------------------------------------
// MLP + gate matrices + sigmoid table (unchanged, proven).
// ---------------------------------------------------------------------------
__global__ void mlp_kernel(const float* __restrict__ X,
                           const float* __restrict__ rot,
                           const float* __restrict__ ent,
                           const float* __restrict__ W1,
                           const float* __restrict__ b1,
                           const float* __restrict__ W2,
                           const float* __restrict__ b2)
{
    __shared__ float sx[100];
    __shared__ float sa[64];
    __shared__ float sh[16];
    const int b = blockIdx.x;
    const int j = threadIdx.x;

    if (b == 0 && j < 45) g_P[j] = sigm(ent[j]);

    for (int k = j; k < 100; k += 64) sx[k] = X[b * 100 + k];
    __syncthreads();
    {
        float s = b1[j];
        #pragma unroll 4
        for (int k = 0; k < 100; k++) s = fmaf(sx[k], W1[k * 64 + j], s);
        sa[j] = s > 0.f ? s : 0.f;
    }
    __syncthreads();
    if (j < 16) {
        float s = b2[j];
        #pragma unroll 8
        for (int k = 0; k < 64; k++) s = fmaf(sa[k], W2[k * 16 + j], s);
        sh[j] = tanhf(s);
    }
    __syncthreads();
    if (j < 48) {
        const int l = j >> 4, q = j & 15;
        float hv = 0.5f * sh[q];
        float ax = rot[(l * 16 + q) * 3 + 0] * hv;
        float ay = rot[(l * 16 + q) * 3 + 1] * hv;
        float az = rot[(l * 16 + q) * 3 + 2] * hv;
        float cx, sx2, cy, sy, cz, sz;
        sincosf(ax, &sx2, &cx);
        sincosf(ay, &sy,  &cy);
        sincosf(az, &sz,  &cz);
        float* m = &g_M[((b * 3 + l) * NQ + q) * 4];
        m[0] =  cx * cy * cz;
        m[1] = -sx2 * sy * sz;
        m[2] =  sx2 * sy * cz;
        m[3] =  cx * cy * sz;
    }
}

// ---------------------------------------------------------------------------
// Layer-0 closed form (unchanged, proven): F' (2048), H_0/H_1 (32 each).
// ---------------------------------------------------------------------------
__global__ void __launch_bounds__(256) prep_kernel()
{
    __shared__ float fA[2048], fB[2048];
    __shared__ float gg[2][32];
    const int b = blockIdx.x;
    const unsigned t = threadIdx.x;
    const float* M = &g_M[b * 3 * 64];

    float ph = 1.f;
    #pragma unroll
    for (int q = 3; q < 11; q++) ph *= M[q * 4 + (((t >> (q - 3)) & 1) ? 2 : 0)];
    #pragma unroll
    for (int r = 0; r < 8; r++) {
        float pr = ph;
        pr *= M[0 + ((r & 1) ? 2 : 0)];
        pr *= M[4 + ((r & 2) ? 2 : 0)];
        pr *= M[8 + ((r & 4) ? 2 : 0)];
        fA[t * 8 + r] = pr;
    }
    __syncthreads();

    float* cur = fA;
    float* nxt = fB;
    #pragma unroll
    for (int i = 0; i < 10; i++) {
        const float p = g_P[i], om = 1.f - p;
        const unsigned cb = 1u << i, tb = 1u << (i + 1);
        #pragma unroll
        for (int k = 0; k < 8; k++) {
            const unsigned l = t + 256u * k;
            const float a = cur[l];
            nxt[l] = (l & cb) ? (om * a + p * cur[l ^ tb]) : a;
        }
        __syncthreads();
        float* tmp = cur; cur = nxt; nxt = tmp;
    }
    #pragma unroll
    for (int k = 0; k < 8; k++) {
        const unsigned l = t + 256u * k;
        g_F[b * 2048 + l] = cur[l];
    }

    if (t < 32) {
        float g = 1.f;
        #pragma unroll
        for (int q = 11; q < 16; q++) g *= M[q * 4 + (((t >> (q - 11)) & 1) ? 2 : 0)];
        gg[0][t] = g;
    }
    __syncthreads();
    if (t < 32) {
        const float p = g_P[10];
        gg[1][t] = (1.f - p) * gg[0][t] + p * gg[0][t ^ 1u];
    }
    __syncthreads();
    #pragma unroll
    for (int i = 11; i < 15; i++) {
        const float p = g_P[i], om = 1.f - p;
        const unsigned cb = 1u << (i - 11), tb = 1u << (i - 10);
        float r = 0.f;
        if (t < 64) {
            const unsigned vv = t >> 5, h = t & 31u;
            const float a = gg[vv][h];
            r = (h & cb) ? (om * a + p * gg[vv][h ^ tb]) : a;
        }
        __syncthreads();
        if (t < 64) gg[t >> 5][t & 31u] = r;
        __syncthreads();
    }
    if (t < 64) g_H[b * 64 + t] = gg[t >> 5][t & 31u];
}

// ---------------------------------------------------------------------------
// Coefficient kernel: all 16-dim hi-side algebra. One thread per batch.
// Order: [layer1] G12..15, C11-split, C12..14; [layer2] G12..15, C11-split,
// C12..14. Output g_U[b][j=cv*2+w][w2][hi].
// ---------------------------------------------------------------------------
__global__ void coef_kernel()
{
    const int b = blockIdx.x * blockDim.x + threadIdx.x;
    if (b >= BATCH) return;
    const float* M1 = &g_M[(b * 3 + 1) * 64];
    const float* M2 = &g_M[(b * 3 + 2) * 64];
    const float* P1 = &g_P[15];
    const float* P2 = &g_P[30];

    float W[4][16];
    for (int term = 0; term < 4; term++) {
        const int c = term & 1, v = term >> 1;
        for (int h = 0; h < 16; h++)
            W[term][h] = g_H[b * 64 + c * 32 + ((h << 1) | v)];
        // layer-1 G12..15
        for (int g = 0; g < 4; g++) {
            const float m00 = M1[48+4*g], m01 = M1[49+4*g],
                        m10 = M1[50+4*g], m11 = M1[51+4*g];
            for (int h = 0; h < 16; h++) if (!(h & (1 << g))) {
                const int j2 = h | (1 << g);
                const float a = W[term][h], d = W[term][j2];
                W[term][h]  = m00 * a + m01 * d;
                W[term][j2] = m10 * a + m11 * d;
            }
        }
    }
    // layer-1 C11 split (tgt = hi bit 0)
    float U[8][16];
    {
        const float p = P1[11], om = 1.f - p;
        for (int term = 0; term < 4; term++)
            for (int h = 0; h < 16; h++) {
                U[term*2][h]   = W[term][h];
                U[term*2+1][h] = om * W[term][h] + p * W[term][h ^ 1];
            }
    }
    // layer-1 C12..C14 (ctrl hi bit q, tgt hi bit q+1)
    for (int j = 0; j < 8; j++)
        for (int q = 0; q < 3; q++) {
            const float p = P1[12+q], om = 1.f - p;
            float tv[16];
            for (int h = 0; h < 16; h++) tv[h] = U[j][h];
            for (int h = 0; h < 16; h++) if (h & (1 << q))
                U[j][h] = om * tv[h] + p * tv[h ^ (2 << q)];
        }
    // layer-2 G12..15
    for (int j = 0; j < 8; j++)
        for (int g = 0; g < 4; g++) {
            const float m00 = M2[48+4*g], m01 = M2[49+4*g],
                        m10 = M2[50+4*g], m11 = M2[51+4*g];
            for (int h = 0; h < 16; h++) if (!(h & (1 << g))) {
                const int j2 = h | (1 << g);
                const float a = U[j][h], d = U[j][j2];
                U[j][h]  = m00 * a + m01 * d;
                U[j][j2] = m10 * a + m11 * d;
            }
        }
    // layer-2 C11 split, then C12..14, store
    const float p2 = P2[11], om2 = 1.f - p2;
    for (int j = 0; j < 8; j++)
        for (int w2 = 0; w2 < 2; w2++) {
            float F[16];
            for (int h = 0; h < 16; h++)
                F[h] = (w2 == 0) ? U[j][h] : (om2 * U[j][h] + p2 * U[j][h ^ 1]);
            for (int q = 0; q < 3; q++) {
                const float p = P2[12+q], om = 1.f - p;
                float tv[16];
                for (int h = 0; h < 16; h++) tv[h] = F[h];
                for (int h = 0; h < 16; h++) if (h & (1 << q))
                    F[h] = om * tv[h] + p * tv[h ^ (2 << q)];
            }
            for (int h = 0; h < 16; h++)
                g_U[b * 256 + j * 32 + w2 * 16 + h] = F[h];
        }
}

// ---------------------------------------------------------------------------
// Stage kernel: one 4096-state basis vector, R13-passA body (proven).
// MODE=1 (stage1): generate Z_{c,v} from F' with mask (b10==c && b11==v),
//   apply layer-1 G0..11 + C0..C10, write Y to g_state[(b*4+term)<<12 ...].
// MODE=0 (stage2): load Y_cv masked to b11==w, apply layer-2 low ops,
//   write V to g_state[VOFF + (b*8+term)<<12 ...].
// ---------------------------------------------------------------------------
#define SMEM_FLOATS 5376
template <int LAYER, int MODE>
__global__ void __launch_bounds__(256) stage_kernel()
{
    __shared__ float sm[SMEM_FLOATS];
    const int term = MODE == 1 ? (blockIdx.x & 3) : (blockIdx.x & 7);
    const int b    = MODE == 1 ? (blockIdx.x >> 2) : (blockIdx.x >> 3);
    const unsigned t = threadIdx.x;
    const float* M = &g_M[(b * 3 + LAYER) * 64];
    const float* P = &g_P[LAYER * 15];

    ull v[8];
    float s[16];
    unsigned obase;

    // ---- load + G0 fold (pack lane = bit 0), with term mask ----
    {
        float m00 = M[0], m01 = M[1], m10 = M[2], m11 = M[3];
        const float* src;
        float maskf;
        if (MODE == 1) {
            const int c = term & 1, vv = term >> 1;
            maskf = (((t >> 6) & 1u) == (unsigned)c && ((t >> 7) & 1u) == (unsigned)vv)
                    ? 1.f : 0.f;
            src = &g_F[(unsigned)b * 2048u + ((t & 127u) << 4)];
            obase = ((unsigned)(b * 4 + term)) << 12;
        } else {
            const int cv = term >> 1, w = term & 1;
            maskf = (((t >> 7) & 1u) == (unsigned)w) ? 1.f : 0.f;
            src = &g_state[((unsigned)(b * 4 + cv) << 12) + (t << 4)];
            obase = VOFF + (((unsigned)(b * 8 + term)) << 12);
        }
        m00 *= maskf; m01 *= maskf; m10 *= maskf; m11 *= maskf;
        #pragma unroll
        for (int k = 0; k < 4; k++) {
            const float4 u = *(const float4*)&src[4 * k];
            v[2*k]   = fpack(fmaf(m00, u.x, m01 * u.y), fmaf(m10, u.x, m11 * u.y));
            v[2*k+1] = fpack(fmaf(m00, u.z, m01 * u.w), fmaf(m10, u.z, m11 * u.w));
        }
    }
    // ---- m0: G1..G3, C0(lane) C1 C2 ----
    gate_p<8>(v, 1, fbcast(M[4]),  fbcast(M[5]),  fbcast(M[6]),  fbcast(M[7]));
    gate_p<8>(v, 2, fbcast(M[8]),  fbcast(M[9]),  fbcast(M[10]), fbcast(M[11]));
    gate_p<8>(v, 4, fbcast(M[12]), fbcast(M[13]), fbcast(M[14]), fbcast(M[15]));
    cnot_p_ext<8>(v, 1, fpack(1.f, 1.f - P[0]), fpack(0.f, P[0]));
    cnot_p<8>(v, 1, 2, fbcast(1.f - P[1]), fbcast(P[1]));
    cnot_p<8>(v, 2, 4, fbcast(1.f - P[2]), fbcast(P[2]));

    // ---- T1 write ----
    #pragma unroll
    for (int i = 0; i < 8; i++) funpack(s[2*i], s[2*i+1], v[i]);
    {
        float4* s4 = (float4*)sm;
        const unsigned w4 = t * 5u + 4u * (t >> 4);
        #pragma unroll
        for (int k = 0; k < 4; k++)
            s4[w4 + k] = make_float4(s[4*k], s[4*k+1], s[4*k+2], s[4*k+3]);
    }
    __syncthreads();
    // ---- T1 read + G4 + C3 fold ----
    {
        const unsigned rbase = (t & 15u) + 336u * (t >> 4);
        const float g00 = M[16], g01 = M[17], g10 = M[18], g11 = M[19];
        const bool c3 = (t & 8u) != 0;
        const float q3 = c3 ? P[3] : 0.f, o3 = 1.f - q3;
        #pragma unroll
        for (int j = 0; j < 8; j++) {
            const float a  = sm[rbase + 20u * (2*j)];
            const float bb = sm[rbase + 20u * (2*j+1)];
            const float lo  = fmaf(g00, a, g01 * bb);
            const float hi2 = fmaf(g10, a, g11 * bb);
            v[j] = fpack(fmaf(o3, lo, q3 * hi2), fmaf(o3, hi2, q3 * lo));
        }
    }
    // ---- m1: G5..G7, C4(lane) C5 C6 ----
    gate_p<8>(v, 1, fbcast(M[20]), fbcast(M[21]), fbcast(M[22]), fbcast(M[23]));
    gate_p<8>(v, 2, fbcast(M[24]), fbcast(M[25]), fbcast(M[26]), fbcast(M[27]));
    gate_p<8>(v, 4, fbcast(M[28]), fbcast(M[29]), fbcast(M[30]), fbcast(M[31]));
    cnot_p_ext<8>(v, 1, fpack(1.f, 1.f - P[4]), fpack(0.f, P[4]));
    cnot_p<8>(v, 1, 2, fbcast(1.f - P[5]), fbcast(P[5]));
    cnot_p<8>(v, 2, 4, fbcast(1.f - P[6]), fbcast(P[6]));

    __syncthreads();

    // ---- T2 write ----
    #pragma unroll
    for (int j = 0; j < 8; j++) funpack(s[2*j], s[2*j+1], v[j]);
    {
        const unsigned wbase = (t & 15u) + 272u * (t >> 4);
        #pragma unroll
        for (int r = 0; r < 16; r++) sm[wbase + 16u * r] = s[r];
    }
    __syncthreads();
    // ---- T2 read + G8 + C7 fold ----
    {
        const float g00 = M[32], g01 = M[33], g10 = M[34], g11 = M[35];
        const bool c7 = (t & 128u) != 0;
        const float q7 = c7 ? P[7] : 0.f, o7 = 1.f - q7;
        #pragma unroll
        for (int j = 0; j < 8; j++) {
            const float a  = sm[272u * (2*j) + t];
            const float bb = sm[272u * (2*j+1) + t];
            const float lo  = fmaf(g00, a, g01 * bb);
            const float hi2 = fmaf(g10, a, g11 * bb);
            v[j] = fpack(fmaf(o7, lo, q7 * hi2), fmaf(o7, hi2, q7 * lo));
        }
    }
    // ---- m2: G9..G11, C8(lane) C9 C10 ----
    gate_p<8>(v, 1, fbcast(M[36]), fbcast(M[37]), fbcast(M[38]), fbcast(M[39]));
    gate_p<8>(v, 2, fbcast(M[40]), fbcast(M[41]), fbcast(M[42]), fbcast(M[43]));
    gate_p<8>(v, 4, fbcast(M[44]), fbcast(M[45]), fbcast(M[46]), fbcast(M[47]));
    cnot_p_ext<8>(v, 1, fpack(1.f, 1.f - P[8]), fpack(0.f, P[8]));
    cnot_p<8>(v, 1, 2, fbcast(1.f - P[9]),  fbcast(P[9]));
    cnot_p<8>(v, 2, 4, fbcast(1.f - P[10]), fbcast(P[10]));

    #pragma unroll
    for (int j = 0; j < 8; j++) {
        float f0, f1;
        funpack(f0, f1, v[j]);
        g_state[obase + ((unsigned)(2*j)   << 8) + t] = f0;
        g_state[obase + ((unsigned)(2*j+1) << 8) + t] = f1;
    }
}

// ---------------------------------------------------------------------------
// Final expansion: out(l,hi) = sum_j V_j(l) * U[b][j][b11(l)][hi].
// Block = 256 l's (chunk) x all 16 hi. Coalesced V reads and output writes.
// ---------------------------------------------------------------------------
__global__ void __launch_bounds__(256) final_kernel(float* __restrict__ outf,
                                                    unsigned capF, int mode)
{
    __shared__ float sU[8][16];
    const int chunk = blockIdx.x & 15;   // l bits 8..11
    const int b = blockIdx.x >> 4;
    const unsigned t = threadIdx.x;
    const unsigned l = ((unsigned)chunk << 8) | t;
    const int w2 = (chunk >> 3) & 1;     // b11(l)

    if (t < 128) sU[t >> 4][t & 15] = g_U[b * 256 + (t >> 4) * 32 + w2 * 16 + (t & 15)];
    __syncthreads();

    float Vv[8];
    #pragma unroll
    for (int j = 0; j < 8; j++)
        Vv[j] = g_state[VOFF + (((unsigned)(b * 8 + j)) << 12) + l];

    #pragma unroll
    for (int hi = 0; hi < 16; hi++) {
        float sres = 0.f;
        #pragma unroll
        for (int j = 0; j < 8; j++) sres = fmaf(Vv[j], sU[j][hi], sres);
        const unsigned idx = ((unsigned)b << 16) | ((unsigned)hi << 12) | l;
        if (mode == 1) {
            const unsigned p2 = 2u * idx;
            if (p2 + 1u < capF) *(float2*)&outf[p2] = make_float2(sres, 0.f);
        } else {
            if (idx < capF) outf[idx] = sres;
        }
    }
}

// ---------------------------------------------------------------------------
extern "C" void kernel_launch(void* const* d_in, const int* in_sizes, int n_in,
                              void* d_out, int out_size)
{
    static const long long want[7] = {25600, 144, 45, 6400, 64, 1024, 16};
    const float* ptr[7] = {0, 0, 0, 0, 0, 0, 0};

    bool bound = false;
    for (int scale = 1; scale <= 4 && !bound; scale *= 4) {
        const float* tmp[7] = {0, 0, 0, 0, 0, 0, 0};
        int m = 0;
        for (int i = 0; i < n_in; i++) {
            long long s = (long long)in_sizes[i];
            for (int j = 0; j < 7; j++) {
                if (!tmp[j] && s == want[j] * scale) { tmp[j] = (const float*)d_in[i]; m++; break; }
            }
        }
        if (m == 7) { for (int j = 0; j < 7; j++) ptr[j] = tmp[j]; bound = true; }
    }
    if (!bound && n_in >= 7) {
        for (int j = 0; j < 7; j++) ptr[j] = (const float*)d_in[j];
        bound = true;
    }

    float* outf = (float*)d_out;

    long long os = (long long)out_size;
    unsigned capF;
    int mode;
    if (os >= 33554432LL)      { mode = 1; capF = 33554432u; }
    else if (os == 16777216LL) { mode = 0; capF = 16777216u; }
    else {
        mode = 0;
        long long c = os > 0 ? os : 0;
        if (c > 33554432LL) c = 33554432LL;
        capF = (unsigned)c;
    }

    if (!bound || !outf) {
        dummy_kernel<<<1, 32>>>(outf, capF);
        return;
    }

    mlp_kernel<<<BATCH, 64>>>(ptr[0], ptr[1], ptr[2], ptr[3], ptr[4], ptr[5], ptr[6]);
    prep_kernel<<<BATCH, 256>>>();
    coef_kernel<<<1, BATCH>>>();

    stage_kernel<1, 1><<<4 * BATCH, 256>>>();   // Y_{c,v} = A1op(Z_{c,v})
    stage_kernel<2, 0><<<8 * BATCH, 256>>>();   // V_j = A2op(Y halves)
    final_kernel<<<16 * BATCH, 256>>>(outf, capF, mode);
}

// round 15
// speedup vs baseline: 1.9859x; 1.5584x over previous
#include <cuda_runtime.h>
#include <math.h>

#define NQ 16
#define NS 65536
#define BATCH 256
#define SLIM (BATCH * NS)
#define MLIM (BATCH * 3 * NQ * 4)
#define VOFF 4194304u   /* V region offset (floats) inside g_state */

__device__ __align__(16) float g_state[SLIM];   // V: [VOFF, VOFF+8M)
__device__ __align__(16) float g_M[MLIM];
__device__ float g_P[48];
__device__ __align__(16) float g_F[BATCH * 2048];
__device__ __align__(16) float g_H[BATCH * 64];
__device__ __align__(16) float g_U[BATCH * 256];  // [b][j:8][w2:2][hi:16]

typedef unsigned long long ull;

__device__ __forceinline__ float sigm(float x) { return 1.0f / (1.0f + expf(-x)); }

// ---- packed f32x2 primitives ----
__device__ __forceinline__ ull fpack(float x, float y) {
    ull r; asm("mov.b64 %0, {%1, %2};" : "=l"(r) : "f"(x), "f"(y)); return r;
}
__device__ __forceinline__ ull fbcast(float x) { return fpack(x, x); }
__device__ __forceinline__ void funpack(float& x, float& y, ull a) {
    asm("mov.b64 {%0, %1}, %2;" : "=f"(x), "=f"(y) : "l"(a));
}
__device__ __forceinline__ ull fma2(ull a, ull b, ull c) {
    ull d; asm("fma.rn.f32x2 %0, %1, %2, %3;" : "=l"(d) : "l"(a), "l"(b), "l"(c)); return d;
}
__device__ __forceinline__ ull mul2(ull a, ull b) {
    ull d; asm("mul.rn.f32x2 %0, %1, %2;" : "=l"(d) : "l"(a), "l"(b)); return d;
}

template <int N>
__device__ __forceinline__ void gate_p(ull* v, int kb, ull M00, ull M01, ull M10, ull M11) {
    #pragma unroll
    for (int i = 0; i < N; i++) if (!(i & kb)) {
        const int j = i | kb;
        ull a = v[i], c = v[j];
        v[i] = fma2(M01, c, mul2(M00, a));
        v[j] = fma2(M11, c, mul2(M10, a));
    }
}
template <int N>
__device__ __forceinline__ void cnot_p(ull* v, int cb, int tb, ull OM, ull PP) {
    #pragma unroll
    for (int i = 0; i < N; i++) if ((i & cb) && !(i & tb)) {
        const int j = i | tb;
        ull a = v[i], c = v[j];
        v[i] = fma2(PP, c, mul2(OM, a));
        v[j] = fma2(PP, a, mul2(OM, c));
    }
}
template <int N>
__device__ __forceinline__ void cnot_p_ext(ull* v, int tb, ull OM, ull PP) {
    #pragma unroll
    for (int i = 0; i < N; i++) if (!(i & tb)) {
        const int j = i | tb;
        ull a = v[i], c = v[j];
        v[i] = fma2(PP, c, mul2(OM, a));
        v[j] = fma2(PP, a, mul2(OM, c));
    }
}

__global__ void dummy_kernel(float* outf, unsigned capF) {
    if (capF > 0) outf[0] = 0.f;
}

// ---------------------------------------------------------------------------
// MLP + gate matrices + sigmoid table (unchanged, proven).
// ---------------------------------------------------------------------------
__global__ void mlp_kernel(const float* __restrict__ X,
                           const float* __restrict__ rot,
                           const float* __restrict__ ent,
                           const float* __restrict__ W1,
                           const float* __restrict__ b1,
                           const float* __restrict__ W2,
                           const float* __restrict__ b2)
{
    __shared__ float sx[100];
    __shared__ float sa[64];
    __shared__ float sh[16];
    const int b = blockIdx.x;
    const int j = threadIdx.x;

    if (b == 0 && j < 45) g_P[j] = sigm(ent[j]);

    for (int k = j; k < 100; k += 64) sx[k] = X[b * 100 + k];
    __syncthreads();
    {
        float s = b1[j];
        #pragma unroll 4
        for (int k = 0; k < 100; k++) s = fmaf(sx[k], W1[k * 64 + j], s);
        sa[j] = s > 0.f ? s : 0.f;
    }
    __syncthreads();
    if (j < 16) {
        float s = b2[j];
        #pragma unroll 8
        for (int k = 0; k < 64; k++) s = fmaf(sa[k], W2[k * 16 + j], s);
        sh[j] = tanhf(s);
    }
    __syncthreads();
    if (j < 48) {
        const int l = j >> 4, q = j & 15;
        float hv = 0.5f * sh[q];
        float ax = rot[(l * 16 + q) * 3 + 0] * hv;
        float ay = rot[(l * 16 + q) * 3 + 1] * hv;
        float az = rot[(l * 16 + q) * 3 + 2] * hv;
        float cx, sx2, cy, sy, cz, sz;
        sincosf(ax, &sx2, &cx);
        sincosf(ay, &sy,  &cy);
        sincosf(az, &sz,  &cz);
        float* m = &g_M[((b * 3 + l) * NQ + q) * 4];
        m[0] =  cx * cy * cz;
        m[1] = -sx2 * sy * sz;
        m[2] =  sx2 * sy * cz;
        m[3] =  cx * cy * sz;
    }
}

// ---------------------------------------------------------------------------
// Layer-0 closed form (unchanged, proven): F' (2048), H_0/H_1 (32 each).
// ---------------------------------------------------------------------------
__global__ void __launch_bounds__(256) prep_kernel()
{
    __shared__ float fA[2048], fB[2048];
    __shared__ float gg[2][32];
    const int b = blockIdx.x;
    const unsigned t = threadIdx.x;
    const float* M = &g_M[b * 3 * 64];

    float ph = 1.f;
    #pragma unroll
    for (int q = 3; q < 11; q++) ph *= M[q * 4 + (((t >> (q - 3)) & 1) ? 2 : 0)];
    #pragma unroll
    for (int r = 0; r < 8; r++) {
        float pr = ph;
        pr *= M[0 + ((r & 1) ? 2 : 0)];
        pr *= M[4 + ((r & 2) ? 2 : 0)];
        pr *= M[8 + ((r & 4) ? 2 : 0)];
        fA[t * 8 + r] = pr;
    }
    __syncthreads();

    float* cur = fA;
    float* nxt = fB;
    #pragma unroll
    for (int i = 0; i < 10; i++) {
        const float p = g_P[i], om = 1.f - p;
        const unsigned cb = 1u << i, tb = 1u << (i + 1);
        #pragma unroll
        for (int k = 0; k < 8; k++) {
            const unsigned l = t + 256u * k;
            const float a = cur[l];
            nxt[l] = (l & cb) ? (om * a + p * cur[l ^ tb]) : a;
        }
        __syncthreads();
        float* tmp = cur; cur = nxt; nxt = tmp;
    }
    #pragma unroll
    for (int k = 0; k < 8; k++) {
        const unsigned l = t + 256u * k;
        g_F[b * 2048 + l] = cur[l];
    }

    if (t < 32) {
        float g = 1.f;
        #pragma unroll
        for (int q = 11; q < 16; q++) g *= M[q * 4 + (((t >> (q - 11)) & 1) ? 2 : 0)];
        gg[0][t] = g;
    }
    __syncthreads();
    if (t < 32) {
        const float p = g_P[10];
        gg[1][t] = (1.f - p) * gg[0][t] + p * gg[0][t ^ 1u];
    }
    __syncthreads();
    #pragma unroll
    for (int i = 11; i < 15; i++) {
        const float p = g_P[i], om = 1.f - p;
        const unsigned cb = 1u << (i - 11), tb = 1u << (i - 10);
        float r = 0.f;
        if (t < 64) {
            const unsigned vv = t >> 5, h = t & 31u;
            const float a = gg[vv][h];
            r = (h & cb) ? (om * a + p * gg[vv][h ^ tb]) : a;
        }
        __syncthreads();
        if (t < 64) gg[t >> 5][t & 31u] = r;
        __syncthreads();
    }
    if (t < 64) g_H[b * 64 + t] = gg[t >> 5][t & 31u];
}

// ---------------------------------------------------------------------------
// Coefficient kernel, parallel: thread = (b, j), 8 blocks x 256 threads.
// Each thread computes its own U_j end-to-end (<= 64 floats live, no spill).
// ---------------------------------------------------------------------------
__global__ void coef_kernel()
{
    const int tid = blockIdx.x * blockDim.x + threadIdx.x;
    if (tid >= BATCH * 8) return;
    const int b = tid >> 3, j = tid & 7;
    const int term = j >> 1;                 // cv
    const int c = term & 1, v = term >> 1;
    const float* M1 = &g_M[(b * 3 + 1) * 64];
    const float* M2 = &g_M[(b * 3 + 2) * 64];
    const float* P1 = &g_P[15];
    const float* P2 = &g_P[30];

    // W = H_c restricted to b11=v, through layer-1 G12..15
    float W[16];
    #pragma unroll
    for (int h = 0; h < 16; h++) W[h] = g_H[b * 64 + c * 32 + ((h << 1) | v)];
    #pragma unroll
    for (int g = 0; g < 4; g++) {
        const float m00 = M1[48+4*g], m01 = M1[49+4*g],
                    m10 = M1[50+4*g], m11 = M1[51+4*g];
        #pragma unroll
        for (int h = 0; h < 16; h++) if (!(h & (1 << g))) {
            const int j2 = h | (1 << g);
            const float a = W[h], d = W[j2];
            W[h]  = m00 * a + m01 * d;
            W[j2] = m10 * a + m11 * d;
        }
    }
    // layer-1 C11 split: j even -> W; j odd -> om*W + p*W(hi^1)
    float U[16];
    {
        const float p = P1[11], om = 1.f - p;
        #pragma unroll
        for (int h = 0; h < 16; h++)
            U[h] = (j & 1) ? (om * W[h] + p * W[h ^ 1]) : W[h];
    }
    // layer-1 C12..C14
    #pragma unroll
    for (int q = 0; q < 3; q++) {
        const float p = P1[12+q], om = 1.f - p;
        float tv[16];
        #pragma unroll
        for (int h = 0; h < 16; h++) tv[h] = U[h];
        #pragma unroll
        for (int h = 0; h < 16; h++) if (h & (1 << q))
            U[h] = om * tv[h] + p * tv[h ^ (2 << q)];
    }
    // layer-2 G12..15
    #pragma unroll
    for (int g = 0; g < 4; g++) {
        const float m00 = M2[48+4*g], m01 = M2[49+4*g],
                    m10 = M2[50+4*g], m11 = M2[51+4*g];
        #pragma unroll
        for (int h = 0; h < 16; h++) if (!(h & (1 << g))) {
            const int j2 = h | (1 << g);
            const float a = U[h], d = U[j2];
            U[h]  = m00 * a + m01 * d;
            U[j2] = m10 * a + m11 * d;
        }
    }
    // layer-2 C11 split + C12..14, store both w2 variants
    const float p2 = P2[11], om2 = 1.f - p2;
    #pragma unroll
    for (int w2 = 0; w2 < 2; w2++) {
        float F[16];
        #pragma unroll
        for (int h = 0; h < 16; h++)
            F[h] = (w2 == 0) ? U[h] : (om2 * U[h] + p2 * U[h ^ 1]);
        #pragma unroll
        for (int q = 0; q < 3; q++) {
            const float p = P2[12+q], om = 1.f - p;
            float tv[16];
            #pragma unroll
            for (int h = 0; h < 16; h++) tv[h] = F[h];
            #pragma unroll
            for (int h = 0; h < 16; h++) if (h & (1 << q))
                F[h] = om * tv[h] + p * tv[h ^ (2 << q)];
        }
        #pragma unroll
        for (int h = 0; h < 16; h++)
            g_U[b * 256 + j * 32 + w2 * 16 + h] = F[h];
    }
}

// ---------------------------------------------------------------------------
// Fused stage kernel: one block per (b, cv). Body-1 applies layer-1 low ops
// to Z_cv; T3 transpose (with layer-2 G0 fold) returns it to m0 layout in
// registers y[8]; then for w = 0,1 body-2 applies layer-2 low ops to the
// b11=w half (mask folded into G1 coefficients) and writes V_{cv*2+w}.
// T3 addressing: addr(idx) = idx + 4*(idx>>4). Write (idx = m<<8|t):
// addr = 320m + t + 4*(t>>4). Read (idx = 16t+k): addr = 20t + k (float4
// reads conflict-free: 8-lane phase covers all 32 banks).
// ---------------------------------------------------------------------------
#define SMEM_FLOATS 5376
template <int DUMMY>
__global__ void __launch_bounds__(256) fused_stage_kernel()
{
    __shared__ float sm[SMEM_FLOATS];
    const int cv = blockIdx.x & 3;
    const int b  = blockIdx.x >> 2;
    const unsigned t = threadIdx.x;
    const float* M1 = &g_M[(b * 3 + 1) * 64];
    const float* M2 = &g_M[(b * 3 + 2) * 64];
    const float* P1 = &g_P[15];
    const float* P2 = &g_P[30];

    ull v[8];

    // ================= body 1: layer-1 low ops on Z_cv =================
    {
        const int c = cv & 1, vv = cv >> 1;
        const float maskf = (((t >> 6) & 1u) == (unsigned)c &&
                             ((t >> 7) & 1u) == (unsigned)vv) ? 1.f : 0.f;
        const float m00 = M1[0] * maskf, m01 = M1[1] * maskf,
                    m10 = M1[2] * maskf, m11 = M1[3] * maskf;
        const float* src = &g_F[(unsigned)b * 2048u + ((t & 127u) << 4)];
        #pragma unroll
        for (int k = 0; k < 4; k++) {
            const float4 u = *(const float4*)&src[4 * k];
            v[2*k]   = fpack(fmaf(m00, u.x, m01 * u.y), fmaf(m10, u.x, m11 * u.y));
            v[2*k+1] = fpack(fmaf(m00, u.z, m01 * u.w), fmaf(m10, u.z, m11 * u.w));
        }
    }
    gate_p<8>(v, 1, fbcast(M1[4]),  fbcast(M1[5]),  fbcast(M1[6]),  fbcast(M1[7]));
    gate_p<8>(v, 2, fbcast(M1[8]),  fbcast(M1[9]),  fbcast(M1[10]), fbcast(M1[11]));
    gate_p<8>(v, 4, fbcast(M1[12]), fbcast(M1[13]), fbcast(M1[14]), fbcast(M1[15]));
    cnot_p_ext<8>(v, 1, fpack(1.f, 1.f - P1[0]), fpack(0.f, P1[0]));
    cnot_p<8>(v, 1, 2, fbcast(1.f - P1[1]), fbcast(P1[1]));
    cnot_p<8>(v, 2, 4, fbcast(1.f - P1[2]), fbcast(P1[2]));

    // T1
    {
        float s0, s1;
        float4* s4 = (float4*)sm;
        const unsigned w4 = t * 5u + 4u * (t >> 4);
        #pragma unroll
        for (int k = 0; k < 4; k++) {
            float a0, a1, a2, a3;
            funpack(a0, a1, v[2*k]);
            funpack(a2, a3, v[2*k+1]);
            s4[w4 + k] = make_float4(a0, a1, a2, a3);
        }
        (void)s0; (void)s1;
    }
    __syncthreads();
    {
        const unsigned rbase = (t & 15u) + 336u * (t >> 4);
        const float g00 = M1[16], g01 = M1[17], g10 = M1[18], g11 = M1[19];
        const bool c3 = (t & 8u) != 0;
        const float q3 = c3 ? P1[3] : 0.f, o3 = 1.f - q3;
        #pragma unroll
        for (int j = 0; j < 8; j++) {
            const float a  = sm[rbase + 20u * (2*j)];
            const float bb = sm[rbase + 20u * (2*j+1)];
            const float lo  = fmaf(g00, a, g01 * bb);
            const float hi2 = fmaf(g10, a, g11 * bb);
            v[j] = fpack(fmaf(o3, lo, q3 * hi2), fmaf(o3, hi2, q3 * lo));
        }
    }
    gate_p<8>(v, 1, fbcast(M1[20]), fbcast(M1[21]), fbcast(M1[22]), fbcast(M1[23]));
    gate_p<8>(v, 2, fbcast(M1[24]), fbcast(M1[25]), fbcast(M1[26]), fbcast(M1[27]));
    gate_p<8>(v, 4, fbcast(M1[28]), fbcast(M1[29]), fbcast(M1[30]), fbcast(M1[31]));
    cnot_p_ext<8>(v, 1, fpack(1.f, 1.f - P1[4]), fpack(0.f, P1[4]));
    cnot_p<8>(v, 1, 2, fbcast(1.f - P1[5]), fbcast(P1[5]));
    cnot_p<8>(v, 2, 4, fbcast(1.f - P1[6]), fbcast(P1[6]));
    __syncthreads();
    // T2
    {
        const unsigned wbase = (t & 15u) + 272u * (t >> 4);
        #pragma unroll
        for (int j = 0; j < 8; j++) {
            float f0, f1;
            funpack(f0, f1, v[j]);
            sm[wbase + 16u * (2*j)]     = f0;
            sm[wbase + 16u * (2*j+1)]   = f1;
        }
    }
    __syncthreads();
    {
        const float g00 = M1[32], g01 = M1[33], g10 = M1[34], g11 = M1[35];
        const bool c7 = (t & 128u) != 0;
        const float q7 = c7 ? P1[7] : 0.f, o7 = 1.f - q7;
        #pragma unroll
        for (int j = 0; j < 8; j++) {
            const float a  = sm[272u * (2*j) + t];
            const float bb = sm[272u * (2*j+1) + t];
            const float lo  = fmaf(g00, a, g01 * bb);
            const float hi2 = fmaf(g10, a, g11 * bb);
            v[j] = fpack(fmaf(o7, lo, q7 * hi2), fmaf(o7, hi2, q7 * lo));
        }
    }
    gate_p<8>(v, 1, fbcast(M1[36]), fbcast(M1[37]), fbcast(M1[38]), fbcast(M1[39]));
    gate_p<8>(v, 2, fbcast(M1[40]), fbcast(M1[41]), fbcast(M1[42]), fbcast(M1[43]));
    gate_p<8>(v, 4, fbcast(M1[44]), fbcast(M1[45]), fbcast(M1[46]), fbcast(M1[47]));
    cnot_p_ext<8>(v, 1, fpack(1.f, 1.f - P1[8]), fpack(0.f, P1[8]));
    cnot_p<8>(v, 1, 2, fbcast(1.f - P1[9]),  fbcast(P1[9]));
    cnot_p<8>(v, 2, 4, fbcast(1.f - P1[10]), fbcast(P1[10]));

    __syncthreads();   // T2 reads done before T3 writes

    // ================= T3: back to m0 layout + layer-2 G0 fold =========
    // write: idx = m<<8 | t  ->  addr = 320*m + t + 4*(t>>4)
    {
        const unsigned wb = t + 4u * (t >> 4);
        #pragma unroll
        for (int j = 0; j < 8; j++) {
            float f0, f1;
            funpack(f0, f1, v[j]);
            sm[320u * (2*j)   + wb] = f0;
            sm[320u * (2*j+1) + wb] = f1;
        }
    }
    __syncthreads();
    // read: idx = 16t + 4k (+0..3) -> addr = 20t + 4k; fold layer-2 G0
    ull y[8];
    {
        const float g00 = M2[0], g01 = M2[1], g10 = M2[2], g11 = M2[3];
        #pragma unroll
        for (int k = 0; k < 4; k++) {
            const float4 u = *(const float4*)&sm[20u * t + 4u * k];
            y[2*k]   = fpack(fmaf(g00, u.x, g01 * u.y), fmaf(g10, u.x, g11 * u.y));
            y[2*k+1] = fpack(fmaf(g00, u.z, g01 * u.w), fmaf(g10, u.z, g11 * u.w));
        }
    }

    // ================= body 2 (x2): layer-2 low ops on b11=w halves ====
    #pragma unroll
    for (int w = 0; w < 2; w++) {
        __syncthreads();   // sm safe to reuse (T3 read / previous T2 read done)
        const float maskf = (((t >> 7) & 1u) == (unsigned)w) ? 1.f : 0.f;
        #pragma unroll
        for (int j = 0; j < 8; j++) v[j] = y[j];
        // G1 with mask folded into coefficients
        gate_p<8>(v, 1, fbcast(M2[4] * maskf), fbcast(M2[5] * maskf),
                        fbcast(M2[6] * maskf), fbcast(M2[7] * maskf));
        gate_p<8>(v, 2, fbcast(M2[8]),  fbcast(M2[9]),  fbcast(M2[10]), fbcast(M2[11]));
        gate_p<8>(v, 4, fbcast(M2[12]), fbcast(M2[13]), fbcast(M2[14]), fbcast(M2[15]));
        cnot_p_ext<8>(v, 1, fpack(1.f, 1.f - P2[0]), fpack(0.f, P2[0]));
        cnot_p<8>(v, 1, 2, fbcast(1.f - P2[1]), fbcast(P2[1]));
        cnot_p<8>(v, 2, 4, fbcast(1.f - P2[2]), fbcast(P2[2]));

        {
            float4* s4 = (float4*)sm;
            const unsigned w4 = t * 5u + 4u * (t >> 4);
            #pragma unroll
            for (int k = 0; k < 4; k++) {
                float a0, a1, a2, a3;
                funpack(a0, a1, v[2*k]);
                funpack(a2, a3, v[2*k+1]);
                s4[w4 + k] = make_float4(a0, a1, a2, a3);
            }
        }
        __syncthreads();
        {
            const unsigned rbase = (t & 15u) + 336u * (t >> 4);
            const float g00 = M2[16], g01 = M2[17], g10 = M2[18], g11 = M2[19];
            const bool c3 = (t & 8u) != 0;
            const float q3 = c3 ? P2[3] : 0.f, o3 = 1.f - q3;
            #pragma unroll
            for (int j = 0; j < 8; j++) {
                const float a  = sm[rbase + 20u * (2*j)];
                const float bb = sm[rbase + 20u * (2*j+1)];
                const float lo  = fmaf(g00, a, g01 * bb);
                const float hi2 = fmaf(g10, a, g11 * bb);
                v[j] = fpack(fmaf(o3, lo, q3 * hi2), fmaf(o3, hi2, q3 * lo));
            }
        }
        gate_p<8>(v, 1, fbcast(M2[20]), fbcast(M2[21]), fbcast(M2[22]), fbcast(M2[23]));
        gate_p<8>(v, 2, fbcast(M2[24]), fbcast(M2[25]), fbcast(M2[26]), fbcast(M2[27]));
        gate_p<8>(v, 4, fbcast(M2[28]), fbcast(M2[29]), fbcast(M2[30]), fbcast(M2[31]));
        cnot_p_ext<8>(v, 1, fpack(1.f, 1.f - P2[4]), fpack(0.f, P2[4]));
        cnot_p<8>(v, 1, 2, fbcast(1.f - P2[5]), fbcast(P2[5]));
        cnot_p<8>(v, 2, 4, fbcast(1.f - P2[6]), fbcast(P2[6]));
        __syncthreads();
        {
            const unsigned wbase = (t & 15u) + 272u * (t >> 4);
            #pragma unroll
            for (int j = 0; j < 8; j++) {
                float f0, f1;
                funpack(f0, f1, v[j]);
                sm[wbase + 16u * (2*j)]   = f0;
                sm[wbase + 16u * (2*j+1)] = f1;
            }
        }
        __syncthreads();
        {
            const float g00 = M2[32], g01 = M2[33], g10 = M2[34], g11 = M2[35];
            const bool c7 = (t & 128u) != 0;
            const float q7 = c7 ? P2[7] : 0.f, o7 = 1.f - q7;
            #pragma unroll
            for (int j = 0; j < 8; j++) {
                const float a  = sm[272u * (2*j) + t];
                const float bb = sm[272u * (2*j+1) + t];
                const float lo  = fmaf(g00, a, g01 * bb);
                const float hi2 = fmaf(g10, a, g11 * bb);
                v[j] = fpack(fmaf(o7, lo, q7 * hi2), fmaf(o7, hi2, q7 * lo));
            }
        }
        gate_p<8>(v, 1, fbcast(M2[36]), fbcast(M2[37]), fbcast(M2[38]), fbcast(M2[39]));
        gate_p<8>(v, 2, fbcast(M2[40]), fbcast(M2[41]), fbcast(M2[42]), fbcast(M2[43]));
        gate_p<8>(v, 4, fbcast(M2[44]), fbcast(M2[45]), fbcast(M2[46]), fbcast(M2[47]));
        cnot_p_ext<8>(v, 1, fpack(1.f, 1.f - P2[8]), fpack(0.f, P2[8]));
        cnot_p<8>(v, 1, 2, fbcast(1.f - P2[9]),  fbcast(P2[9]));
        cnot_p<8>(v, 2, 4, fbcast(1.f - P2[10]), fbcast(P2[10]));

        const unsigned obase = VOFF + (((unsigned)(b * 8 + cv * 2 + w)) << 12);
        #pragma unroll
        for (int j = 0; j < 8; j++) {
            float f0, f1;
            funpack(f0, f1, v[j]);
            g_state[obase + ((unsigned)(2*j)   << 8) + t] = f0;
            g_state[obase + ((unsigned)(2*j+1) << 8) + t] = f1;
        }
    }
}

// ---------------------------------------------------------------------------
// Final expansion, 2-wide: out(l,hi) = sum_j V_j(l) * U[b][j][b11(l)][hi].
// Block covers 512 l's (chunk = l bits 9..11); thread handles l = 2t, 2t+1.
// ---------------------------------------------------------------------------
__global__ void __launch_bounds__(256) final_kernel(float* __restrict__ outf,
                                                    unsigned capF, int mode)
{
    __shared__ float sU[8][16];
    const int chunk = blockIdx.x & 7;    // l bits 9..11
    const int b = blockIdx.x >> 3;
    const unsigned t = threadIdx.x;
    const unsigned l = ((unsigned)chunk << 9) | (t << 1);
    const int w2 = chunk >> 2;           // b11(l)

    if (t < 128) sU[t >> 4][t & 15] = g_U[b * 256 + (t >> 4) * 32 + w2 * 16 + (t & 15)];
    __syncthreads();

    float V0[8], V1[8];
    #pragma unroll
    for (int j = 0; j < 8; j++) {
        const float2 u = *(const float2*)&g_state[VOFF + (((unsigned)(b * 8 + j)) << 12) + l];
        V0[j] = u.x; V1[j] = u.y;
    }

    #pragma unroll
    for (int hi = 0; hi < 16; hi++) {
        float r0 = 0.f, r1 = 0.f;
        #pragma unroll
        for (int j = 0; j < 8; j++) {
            r0 = fmaf(V0[j], sU[j][hi], r0);
            r1 = fmaf(V1[j], sU[j][hi], r1);
        }
        const unsigned idx = ((unsigned)b << 16) | ((unsigned)hi << 12) | l;
        if (mode == 1) {
            const unsigned p2 = 2u * idx;     // idx even -> 16B aligned
            if (p2 + 3u < capF) *(float4*)&outf[p2] = make_float4(r0, 0.f, r1, 0.f);
        } else {
            if (idx + 1u < capF) *(float2*)&outf[idx] = make_float2(r0, r1);
        }
    }
}

// ---------------------------------------------------------------------------
extern "C" void kernel_launch(void* const* d_in, const int* in_sizes, int n_in,
                              void* d_out, int out_size)
{
    static const long long want[7] = {25600, 144, 45, 6400, 64, 1024, 16};
    const float* ptr[7] = {0, 0, 0, 0, 0, 0, 0};

    bool bound = false;
    for (int scale = 1; scale <= 4 && !bound; scale *= 4) {
        const float* tmp[7] = {0, 0, 0, 0, 0, 0, 0};
        int m = 0;
        for (int i = 0; i < n_in; i++) {
            long long s = (long long)in_sizes[i];
            for (int j = 0; j < 7; j++) {
                if (!tmp[j] && s == want[j] * scale) { tmp[j] = (const float*)d_in[i]; m++; break; }
            }
        }
        if (m == 7) { for (int j = 0; j < 7; j++) ptr[j] = tmp[j]; bound = true; }
    }
    if (!bound && n_in >= 7) {
        for (int j = 0; j < 7; j++) ptr[j] = (const float*)d_in[j];
        bound = true;
    }

    float* outf = (float*)d_out;

    long long os = (long long)out_size;
    unsigned capF;
    int mode;
    if (os >= 33554432LL)      { mode = 1; capF = 33554432u; }
    else if (os == 16777216LL) { mode = 0; capF = 16777216u; }
    else {
        mode = 0;
        long long c = os > 0 ? os : 0;
        if (c > 33554432LL) c = 33554432LL;
        capF = (unsigned)c;
    }

    if (!bound || !outf) {
        dummy_kernel<<<1, 32>>>(outf, capF);
        return;
    }

    mlp_kernel<<<BATCH, 64>>>(ptr[0], ptr[1], ptr[2], ptr[3], ptr[4], ptr[5], ptr[6]);
    prep_kernel<<<BATCH, 256>>>();
    coef_kernel<<<8, 256>>>();
    fused_stage_kernel<0><<<4 * BATCH, 256>>>();
    final_kernel<<<8 * BATCH, 256>>>(outf, capF, mode);
}

// round 16
// speedup vs baseline: 2.4740x; 1.2458x over previous
#include <cuda_runtime.h>
#include <math.h>

#define NQ 16
#define BATCH 256
#define SLIM (BATCH * 65536)
#define MLIM (BATCH * 3 * NQ * 4)
#define VOFF 4194304u   /* V region offset (floats) inside g_state */

__device__ __align__(16) float g_state[SLIM];   // Y: [0,1M), V: [VOFF,VOFF+4M)
__device__ __align__(16) float g_M[MLIM];
__device__ float g_P[48];
__device__ __align__(16) float g_F[BATCH * 2048];
__device__ __align__(16) float g_H[BATCH * 64];
__device__ __align__(16) float g_U[BATCH * 1024];  // [b][j:8][b10:2][w2:2][hi:16]

typedef unsigned long long ull;

__device__ __forceinline__ float sigm(float x) { return 1.0f / (1.0f + expf(-x)); }

// ---- packed f32x2 primitives ----
__device__ __forceinline__ ull fpack(float x, float y) {
    ull r; asm("mov.b64 %0, {%1, %2};" : "=l"(r) : "f"(x), "f"(y)); return r;
}
__device__ __forceinline__ ull fbcast(float x) { return fpack(x, x); }
__device__ __forceinline__ void funpack(float& x, float& y, ull a) {
    asm("mov.b64 {%0, %1}, %2;" : "=f"(x), "=f"(y) : "l"(a));
}
__device__ __forceinline__ ull fma2(ull a, ull b, ull c) {
    ull d; asm("fma.rn.f32x2 %0, %1, %2, %3;" : "=l"(d) : "l"(a), "l"(b), "l"(c)); return d;
}
__device__ __forceinline__ ull mul2(ull a, ull b) {
    ull d; asm("mul.rn.f32x2 %0, %1, %2;" : "=l"(d) : "l"(a), "l"(b)); return d;
}

template <int N>
__device__ __forceinline__ void gate_p(ull* v, int kb, ull M00, ull M01, ull M10, ull M11) {
    #pragma unroll
    for (int i = 0; i < N; i++) if (!(i & kb)) {
        const int j = i | kb;
        ull a = v[i], c = v[j];
        v[i] = fma2(M01, c, mul2(M00, a));
        v[j] = fma2(M11, c, mul2(M10, a));
    }
}
template <int N>
__device__ __forceinline__ void cnot_p(ull* v, int cb, int tb, ull OM, ull PP) {
    #pragma unroll
    for (int i = 0; i < N; i++) if ((i & cb) && !(i & tb)) {
        const int j = i | tb;
        ull a = v[i], c = v[j];
        v[i] = fma2(PP, c, mul2(OM, a));
        v[j] = fma2(PP, a, mul2(OM, c));
    }
}
template <int N>
__device__ __forceinline__ void cnot_p_ext(ull* v, int tb, ull OM, ull PP) {
    #pragma unroll
    for (int i = 0; i < N; i++) if (!(i & tb)) {
        const int j = i | tb;
        ull a = v[i], c = v[j];
        v[i] = fma2(PP, c, mul2(OM, a));
        v[j] = fma2(PP, a, mul2(OM, c));
    }
}

__global__ void dummy_kernel(float* outf, unsigned capF) {
    if (capF > 0) outf[0] = 0.f;
}

// ---------------------------------------------------------------------------
// Packed 2048-low sweep body. s-space (4096) = lane (s0) + low bits 0..10
// (s1..s11). Applies gates q0..q10 (s1..s11) and CNOT chain C0..C9
// (s_{i+1} -> s_{i+2}). Phases: m0 regs s1..3 (lane s0), T1, m1 regs s5..7
// (lane s4), T2, m2 regs s9..11 (lane s8). Transposes reuse the R15-proven
// padded addressing. Input: v in m0 layout. Output: v in m2 layout.
// ---------------------------------------------------------------------------
__device__ __forceinline__ void run_body(ull* v, const float* M, const float* P,
                                         float* sm, unsigned t)
{
    // m0: gates q0,q1,q2; C0 (s1->s2), C1 (s2->s3)
    gate_p<8>(v, 1, fbcast(M[0]), fbcast(M[1]), fbcast(M[2]),  fbcast(M[3]));
    gate_p<8>(v, 2, fbcast(M[4]), fbcast(M[5]), fbcast(M[6]),  fbcast(M[7]));
    gate_p<8>(v, 4, fbcast(M[8]), fbcast(M[9]), fbcast(M[10]), fbcast(M[11]));
    cnot_p<8>(v, 1, 2, fbcast(1.f - P[0]), fbcast(P[0]));
    cnot_p<8>(v, 2, 4, fbcast(1.f - P[1]), fbcast(P[1]));

    // T1 write (16 consecutive s floats per thread, float4, padded)
    {
        float4* s4 = (float4*)sm;
        const unsigned w4 = t * 5u + 4u * (t >> 4);
        #pragma unroll
        for (int k = 0; k < 4; k++) {
            float a0, a1, a2, a3;
            funpack(a0, a1, v[2*k]);
            funpack(a2, a3, v[2*k+1]);
            s4[w4 + k] = make_float4(a0, a1, a2, a3);
        }
    }
    __syncthreads();
    // T1 read + gate q3 (s4) fold + C2 fold (ctrl s3 = t&8, tgt s4)
    {
        const unsigned rbase = (t & 15u) + 336u * (t >> 4);
        const float g00 = M[12], g01 = M[13], g10 = M[14], g11 = M[15];
        const bool c2 = (t & 8u) != 0;
        const float q2p = c2 ? P[2] : 0.f, o2 = 1.f - q2p;
        #pragma unroll
        for (int j = 0; j < 8; j++) {
            const float a  = sm[rbase + 20u * (2*j)];
            const float bb = sm[rbase + 20u * (2*j+1)];
            const float lo  = fmaf(g00, a, g01 * bb);
            const float hi2 = fmaf(g10, a, g11 * bb);
            v[j] = fpack(fmaf(o2, lo, q2p * hi2), fmaf(o2, hi2, q2p * lo));
        }
    }
    // m1: gates q4,q5,q6; C3 (lane ctrl s4), C4, C5
    gate_p<8>(v, 1, fbcast(M[16]), fbcast(M[17]), fbcast(M[18]), fbcast(M[19]));
    gate_p<8>(v, 2, fbcast(M[20]), fbcast(M[21]), fbcast(M[22]), fbcast(M[23]));
    gate_p<8>(v, 4, fbcast(M[24]), fbcast(M[25]), fbcast(M[26]), fbcast(M[27]));
    cnot_p_ext<8>(v, 1, fpack(1.f, 1.f - P[3]), fpack(0.f, P[3]));
    cnot_p<8>(v, 1, 2, fbcast(1.f - P[4]), fbcast(P[4]));
    cnot_p<8>(v, 2, 4, fbcast(1.f - P[5]), fbcast(P[5]));

    __syncthreads();  // WAR before buffer reuse

    // T2 write
    {
        const unsigned wbase = (t & 15u) + 272u * (t >> 4);
        #pragma unroll
        for (int j = 0; j < 8; j++) {
            float f0, f1;
            funpack(f0, f1, v[j]);
            sm[wbase + 16u * (2*j)]   = f0;
            sm[wbase + 16u * (2*j+1)] = f1;
        }
    }
    __syncthreads();
    // T2 read + gate q7 (s8) fold + C6 fold (ctrl s7 = t&128, tgt s8)
    {
        const float g00 = M[28], g01 = M[29], g10 = M[30], g11 = M[31];
        const bool c6 = (t & 128u) != 0;
        const float q6p = c6 ? P[6] : 0.f, o6 = 1.f - q6p;
        #pragma unroll
        for (int j = 0; j < 8; j++) {
            const float a  = sm[272u * (2*j) + t];
            const float bb = sm[272u * (2*j+1) + t];
            const float lo  = fmaf(g00, a, g01 * bb);
            const float hi2 = fmaf(g10, a, g11 * bb);
            v[j] = fpack(fmaf(o6, lo, q6p * hi2), fmaf(o6, hi2, q6p * lo));
        }
    }
    // m2: gates q8,q9,q10; C7 (lane ctrl s8), C8, C9
    gate_p<8>(v, 1, fbcast(M[32]), fbcast(M[33]), fbcast(M[34]), fbcast(M[35]));
    gate_p<8>(v, 2, fbcast(M[36]), fbcast(M[37]), fbcast(M[38]), fbcast(M[39]));
    gate_p<8>(v, 4, fbcast(M[40]), fbcast(M[41]), fbcast(M[42]), fbcast(M[43]));
    cnot_p_ext<8>(v, 1, fpack(1.f, 1.f - P[7]), fpack(0.f, P[7]));
    cnot_p<8>(v, 1, 2, fbcast(1.f - P[8]), fbcast(P[8]));
    cnot_p<8>(v, 2, 4, fbcast(1.f - P[9]), fbcast(P[9]));
}

// m2 s-linear store: s = r<<8 | t, r = 2j + lane.
__device__ __forceinline__ void store_m2(const ull* v, float* dst, unsigned t)
{
    #pragma unroll
    for (int j = 0; j < 8; j++) {
        float f0, f1;
        funpack(f0, f1, v[j]);
        dst[((unsigned)(2*j)   << 8) + t] = f0;
        dst[((unsigned)(2*j+1) << 8) + t] = f1;
    }
}

// ---------------------------------------------------------------------------
// Setup: MLP + gate matrices + sigmoid table + layer-0 closed form (F', H).
// One block per batch element, 256 threads. Per-block sigmoids in smem (sp)
// avoid cross-block dependence on g_P.
// ---------------------------------------------------------------------------
__global__ void __launch_bounds__(256) setup_kernel(
    const float* __restrict__ X, const float* __restrict__ rot,
    const float* __restrict__ ent, const float* __restrict__ W1,
    const float* __restrict__ b1, const float* __restrict__ W2,
    const float* __restrict__ b2)
{
    __shared__ float sx[100], sa[64], sh[16], sM[192], sp[15];
    __shared__ float fA[2048], fB[2048];
    __shared__ float gg[2][32];
    const int b = blockIdx.x;
    const unsigned t = threadIdx.x;

    if (t < 15) sp[t] = sigm(ent[t]);
    if (b == 0 && t < 45) g_P[t] = sigm(ent[t]);
    for (int k = t; k < 100; k += 256) sx[k] = X[b * 100 + k];
    __syncthreads();
    if (t < 64) {
        float s = b1[t];
        #pragma unroll 4
        for (int k = 0; k < 100; k++) s = fmaf(sx[k], W1[k * 64 + t], s);
        sa[t] = s > 0.f ? s : 0.f;
    }
    __syncthreads();
    if (t < 16) {
        float s = b2[t];
        #pragma unroll 8
        for (int k = 0; k < 64; k++) s = fmaf(sa[k], W2[k * 16 + t], s);
        sh[t] = tanhf(s);
    }
    __syncthreads();
    if (t < 48) {
        const int l = t >> 4, q = t & 15;
        float hv = 0.5f * sh[q];
        float ax = rot[(l * 16 + q) * 3 + 0] * hv;
        float ay = rot[(l * 16 + q) * 3 + 1] * hv;
        float az = rot[(l * 16 + q) * 3 + 2] * hv;
        float cx, sx2, cy, sy, cz, sz;
        sincosf(ax, &sx2, &cx);
        sincosf(ay, &sy,  &cy);
        sincosf(az, &sz,  &cz);
        const float m0 =  cx * cy * cz;
        const float m1 = -sx2 * sy * sz;
        const float m2 =  sx2 * sy * cz;
        const float m3 =  cx * cy * sz;
        sM[t * 4 + 0] = m0; sM[t * 4 + 1] = m1;
        sM[t * 4 + 2] = m2; sM[t * 4 + 3] = m3;
        float* gm = &g_M[b * 192 + t * 4];
        gm[0] = m0; gm[1] = m1; gm[2] = m2; gm[3] = m3;
    }
    __syncthreads();

    // ---- layer-0 prep: F' ----
    const float* M = sM;  // layer 0
    float ph = 1.f;
    #pragma unroll
    for (int q = 3; q < 11; q++) ph *= M[q * 4 + (((t >> (q - 3)) & 1) ? 2 : 0)];
    #pragma unroll
    for (int r = 0; r < 8; r++) {
        float pr = ph;
        pr *= M[0 + ((r & 1) ? 2 : 0)];
        pr *= M[4 + ((r & 2) ? 2 : 0)];
        pr *= M[8 + ((r & 4) ? 2 : 0)];
        fA[t * 8 + r] = pr;
    }
    __syncthreads();
    float* cur = fA;
    float* nxt = fB;
    #pragma unroll
    for (int i = 0; i < 10; i++) {
        const float p = sp[i], om = 1.f - p;
        const unsigned cb = 1u << i, tb = 1u << (i + 1);
        #pragma unroll
        for (int k = 0; k < 8; k++) {
            const unsigned l = t + 256u * k;
            const float a = cur[l];
            nxt[l] = (l & cb) ? (om * a + p * cur[l ^ tb]) : a;
        }
        __syncthreads();
        float* tmp = cur; cur = nxt; nxt = tmp;
    }
    #pragma unroll
    for (int k = 0; k < 8; k++) {
        const unsigned l = t + 256u * k;
        g_F[b * 2048 + l] = cur[l];
    }

    // ---- layer-0 high factors H_0, H_1 ----
    if (t < 32) {
        float g = 1.f;
        #pragma unroll
        for (int q = 11; q < 16; q++) g *= M[q * 4 + (((t >> (q - 11)) & 1) ? 2 : 0)];
        gg[0][t] = g;
    }
    __syncthreads();
    if (t < 32) {
        const float p = sp[10];
        gg[1][t] = (1.f - p) * gg[0][t] + p * gg[0][t ^ 1u];
    }
    __syncthreads();
    #pragma unroll
    for (int i = 11; i < 15; i++) {
        const float p = sp[i], om = 1.f - p;
        const unsigned cb = 1u << (i - 11), tb = 1u << (i - 10);
        float r = 0.f;
        if (t < 64) {
            const unsigned vv = t >> 5, h = t & 31u;
            const float a = gg[vv][h];
            r = (h & cb) ? (om * a + p * gg[vv][h ^ tb]) : a;
        }
        __syncthreads();
        if (t < 64) gg[t >> 5][t & 31u] = r;
        __syncthreads();
    }
    if (t < 64) g_H[b * 64 + t] = gg[t >> 5][t & 31u];
}

// ---------------------------------------------------------------------------
// Coefficient kernel: thread = (b, j), j = (v<<2)|(c<<1)|w (cv = v*2+c as
// before). Computes U_j[w2][hi] through both layers' hi ops, then folds
// K2(b10, w2; w) from layer-2's G11/C10: g_U[b][j][b10][w2][hi].
// ---------------------------------------------------------------------------
__global__ void coef_kernel()
{
    const int tid = blockIdx.x * blockDim.x + threadIdx.x;
    if (tid >= BATCH * 8) return;
    const int b = tid >> 3, j = tid & 7;
    const int term = j >> 1;               // cv = v*2 + c
    const int c = term & 1, v = term >> 1;
    const int w = j & 1;
    const float* M1 = &g_M[(b * 3 + 1) * 64];
    const float* M2 = &g_M[(b * 3 + 2) * 64];
    const float* P1 = &g_P[15];
    const float* P2 = &g_P[30];

    float W[16];
    #pragma unroll
    for (int h = 0; h < 16; h++) W[h] = g_H[b * 64 + c * 32 + ((h << 1) | v)];
    #pragma unroll
    for (int g = 0; g < 4; g++) {   // layer-1 G12..15
        const float m00 = M1[48+4*g], m01 = M1[49+4*g],
                    m10 = M1[50+4*g], m11 = M1[51+4*g];
        #pragma unroll
        for (int h = 0; h < 16; h++) if (!(h & (1 << g))) {
            const int j2 = h | (1 << g);
            const float a = W[h], d = W[j2];
            W[h]  = m00 * a + m01 * d;
            W[j2] = m10 * a + m11 * d;
        }
    }
    float U[16];
    {   // layer-1 C11 split (hi mixed only on w=1 branch)
        const float p = P1[11], om = 1.f - p;
        #pragma unroll
        for (int h = 0; h < 16; h++)
            U[h] = w ? (om * W[h] + p * W[h ^ 1]) : W[h];
    }
    #pragma unroll
    for (int q = 0; q < 3; q++) {   // layer-1 C12..C14
        const float p = P1[12+q], om = 1.f - p;
        float tv[16];
        #pragma unroll
        for (int h = 0; h < 16; h++) tv[h] = U[h];
        #pragma unroll
        for (int h = 0; h < 16; h++) if (h & (1 << q))
            U[h] = om * tv[h] + p * tv[h ^ (2 << q)];
    }
    #pragma unroll
    for (int g = 0; g < 4; g++) {   // layer-2 G12..15
        const float m00 = M2[48+4*g], m01 = M2[49+4*g],
                    m10 = M2[50+4*g], m11 = M2[51+4*g];
        #pragma unroll
        for (int h = 0; h < 16; h++) if (!(h & (1 << g))) {
            const int j2 = h | (1 << g);
            const float a = U[h], d = U[j2];
            U[h]  = m00 * a + m01 * d;
            U[j2] = m10 * a + m11 * d;
        }
    }
    // layer-2 C11 split (w2) + C12..14, then K2(b10, w2; w) fold, store.
    const float p11 = P2[11], om11 = 1.f - p11;
    const float p10 = P2[10];
    #pragma unroll
    for (int w2 = 0; w2 < 2; w2++) {
        float F[16];
        #pragma unroll
        for (int h = 0; h < 16; h++)
            F[h] = (w2 == 0) ? U[h] : (om11 * U[h] + p11 * U[h ^ 1]);
        #pragma unroll
        for (int q = 0; q < 3; q++) {
            const float p = P2[12+q], om = 1.f - p;
            float tv[16];
            #pragma unroll
            for (int h = 0; h < 16; h++) tv[h] = F[h];
            #pragma unroll
            for (int h = 0; h < 16; h++) if (h & (1 << q))
                F[h] = om * tv[h] + p * tv[h ^ (2 << q)];
        }
        const float K20 = M2[44 + 2*w2 + w];
        const float K21 = (1.f - p10) * K20 + p10 * M2[44 + 2*(1-w2) + w];
        #pragma unroll
        for (int h = 0; h < 16; h++) {
            g_U[b * 1024 + j * 64 +      w2 * 16 + h] = K20 * F[h];  // b10=0
            g_U[b * 1024 + j * 64 + 32 + w2 * 16 + h] = K21 * F[h];  // b10=1
        }
    }
}

// ---------------------------------------------------------------------------
// Stage A: one block per batch. Packed lanes = c (b10 mask). Applies layer-1
// G0..G10 + C0..C9 to x_c = F' * [b10=c], both c simultaneously. Writes Y
// (m2 s-linear, 4096 floats) to g_state[b*4096 ...].
// ---------------------------------------------------------------------------
__global__ void __launch_bounds__(256) stageA_kernel()
{
    __shared__ float sm[5376];
    const int b = blockIdx.x;
    const unsigned t = threadIdx.x;
    const float* M1 = &g_M[(b * 3 + 1) * 64];
    const float* P1 = &g_P[15];

    // load: low = 8t + j; b10(low) = t bit 7. lane0 = c=0, lane1 = c=1.
    ull v[8];
    {
        const bool hi10 = (t & 128u) != 0;
        const float* src = &g_F[(unsigned)b * 2048u + (t << 3)];
        #pragma unroll
        for (int k = 0; k < 2; k++) {
            const float4 u = *(const float4*)&src[4 * k];
            const float f[4] = {u.x, u.y, u.z, u.w};
            #pragma unroll
            for (int m = 0; m < 4; m++) {
                const int j = 4*k + m;
                v[j] = hi10 ? fpack(0.f, f[m]) : fpack(f[m], 0.f);
            }
        }
    }
    run_body(v, M1, P1, sm, t);
    store_m2(v, &g_state[(unsigned)b << 12], t);
}

// ---------------------------------------------------------------------------
// Stage B: block = (b, q), q = v*2 + w. Loads Y (m0 pattern from the s-linear
// global — the round-trip performs the transpose), multiplies by
// kappa = K(b10(low), w; v) from layer-1's G11/C10, applies layer-2
// G0..G10 + C0..C9, writes V_q to g_state[VOFF + (b*4+q)*4096 ...].
// ---------------------------------------------------------------------------
__global__ void __launch_bounds__(256) stageB_kernel()
{
    __shared__ float sm[5376];
    const int q = blockIdx.x & 3;
    const int b = blockIdx.x >> 2;
    const int v2 = q >> 1, w = q & 1;
    const float* M1 = &g_M[(b * 3 + 1) * 64];
    const float* M2 = &g_M[(b * 3 + 2) * 64];
    const float* P2 = &g_P[30];
    const float p10 = g_P[15 + 10];
    const unsigned t = threadIdx.x;

    const float K0 = M1[44 + 2*w + v2];
    const float K1 = (1.f - p10) * K0 + p10 * M1[44 + 2*(1-w) + v2];
    const float kap = (t & 128u) ? K1 : K0;   // b10(low) = t bit 7 in m0

    ull v[8];
    {
        const float* src = &g_state[((unsigned)b << 12) + (t << 4)];
        const ull kk = fbcast(kap);
        #pragma unroll
        for (int k = 0; k < 4; k++) {
            const float4 u = *(const float4*)&src[4 * k];
            v[2*k]   = mul2(fpack(u.x, u.y), kk);
            v[2*k+1] = mul2(fpack(u.z, u.w), kk);
        }
    }
    run_body(v, M2, P2, sm, t);
    store_m2(v, &g_state[VOFF + (((unsigned)(b * 4 + q)) << 12)], t);
}

// ---------------------------------------------------------------------------
// Final expansion: out(l,hi) = sum_{q,c} V_q((low<<1)|c) *
//   Uhat[j(q,c)][b10(low)][b11(l)][hi],  j = (q>>1)*4 + c*2 + (q&1).
// Block = (b, chunk = low bits 9..10); thread owns lows 2t, 2t+1; writes
// 2 b11 x 16 hi x 2 lows outputs. b10 = chunk>>1 (uniform per block).
// ---------------------------------------------------------------------------
__global__ void __launch_bounds__(256) final_kernel(float* __restrict__ outf,
                                                    unsigned capF, int mode)
{
    __shared__ float sU[256];   // [j:8][b11:2][hi:16] for this block's b10
    const int chunk = blockIdx.x & 3;
    const int b = blockIdx.x >> 2;
    const int b10 = chunk >> 1;
    const unsigned t = threadIdx.x;
    const unsigned low0 = ((unsigned)chunk << 9) | (t << 1);

    sU[t] = g_U[b * 1024 + (t >> 5) * 64 + b10 * 32 + (t & 31u)];
    __syncthreads();

    float4 V[4];
    #pragma unroll
    for (int q = 0; q < 4; q++)
        V[q] = *(const float4*)&g_state[VOFF + (((unsigned)(b * 4 + q)) << 12) + (low0 << 1)];

    #pragma unroll
    for (int b11 = 0; b11 < 2; b11++) {
        #pragma unroll
        for (int hi = 0; hi < 16; hi++) {
            float r0 = 0.f, r1 = 0.f;
            #pragma unroll
            for (int q = 0; q < 4; q++) {
                const int j0 = ((q >> 1) << 2) | (q & 1);
                const float u0 = sU[j0 * 32 + b11 * 16 + hi];
                const float u1 = sU[(j0 + 2) * 32 + b11 * 16 + hi];
                r0 = fmaf(V[q].x, u0, r0); r0 = fmaf(V[q].y, u1, r0);
                r1 = fmaf(V[q].z, u0, r1); r1 = fmaf(V[q].w, u1, r1);
            }
            const unsigned idx = ((unsigned)b << 16) | ((unsigned)hi << 12)
                               | ((unsigned)b11 << 11) | low0;
            if (mode == 1) {
                const unsigned p2 = 2u * idx;     // idx even -> 16B aligned
                if (p2 + 4u <= capF) *(float4*)&outf[p2] = make_float4(r0, 0.f, r1, 0.f);
            } else {
                if (idx + 2u <= capF) *(float2*)&outf[idx] = make_float2(r0, r1);
            }
        }
    }
}

// ---------------------------------------------------------------------------
extern "C" void kernel_launch(void* const* d_in, const int* in_sizes, int n_in,
                              void* d_out, int out_size)
{
    static const long long want[7] = {25600, 144, 45, 6400, 64, 1024, 16};
    const float* ptr[7] = {0, 0, 0, 0, 0, 0, 0};

    bool bound = false;
    for (int scale = 1; scale <= 4 && !bound; scale *= 4) {
        const float* tmp[7] = {0, 0, 0, 0, 0, 0, 0};
        int m = 0;
        for (int i = 0; i < n_in; i++) {
            long long s = (long long)in_sizes[i];
            for (int j = 0; j < 7; j++) {
                if (!tmp[j] && s == want[j] * scale) { tmp[j] = (const float*)d_in[i]; m++; break; }
            }
        }
        if (m == 7) { for (int j = 0; j < 7; j++) ptr[j] = tmp[j]; bound = true; }
    }
    if (!bound && n_in >= 7) {
        for (int j = 0; j < 7; j++) ptr[j] = (const float*)d_in[j];
        bound = true;
    }

    float* outf = (float*)d_out;

    long long os = (long long)out_size;
    unsigned capF;
    int mode;
    if (os >= 33554432LL)      { mode = 1; capF = 33554432u; }
    else if (os == 16777216LL) { mode = 0; capF = 16777216u; }
    else {
        mode = 0;
        long long c = os > 0 ? os : 0;
        if (c > 33554432LL) c = 33554432LL;
        capF = (unsigned)c;
    }

    if (!bound || !outf) {
        dummy_kernel<<<1, 32>>>(outf, capF);
        return;
    }

    setup_kernel<<<BATCH, 256>>>(ptr[0], ptr[1], ptr[2], ptr[3], ptr[4], ptr[5], ptr[6]);
    coef_kernel<<<8, 256>>>();
    stageA_kernel<<<BATCH, 256>>>();
    stageB_kernel<<<4 * BATCH, 256>>>();
    final_kernel<<<4 * BATCH, 256>>>(outf, capF, mode);
}